// round 13
// baseline (speedup 1.0000x reference)
#include <cuda_runtime.h>
#include <cuda_bf16.h>
#include <cuda_fp16.h>
#include <math.h>
#include <stdint.h>

// Problem constants (fixed by reference)
#define NN   100000
#define EE   1600000
#define MPAD 100096   // 782 * 128

// ---------------------------------------------------------------------------
// Scratch (__device__ globals; no runtime allocation)
// ---------------------------------------------------------------------------
__device__ __half g_gh[(size_t)MPAD * 256];    // GEMM output (fp16) / SpMM gather input
__device__ __half g_act[(size_t)MPAD * 256];   // activations (fp16) / GEMM A input
__device__ __half g_wf[3 * 256 * 256];         // W^T per layer (n-major, k contig, fp16)
__device__ float  g_h4[(size_t)NN * 16];       // fused layer-4 pre-agg (fp32)
__device__ int    g_deg[NN];
__device__ float  g_dinv[NN];
__device__ int    g_rowptr[NN + 1];
__device__ int    g_cursor[NN];
__device__ int    g_bsum[128];
__device__ int2   g_edges[EE];                 // packed (src, norm-bits)

// ---------------------------------------------------------------------------
// PTX helpers (sm_80-era; valid on plain compute_100 target)
// ---------------------------------------------------------------------------
__device__ __forceinline__ uint32_t smem_u32(const void* p) {
    uint32_t a;
    asm("{ .reg .u64 t; cvta.to.shared.u64 t, %1; cvt.u32.u64 %0, t; }"
        : "=r"(a) : "l"(p));
    return a;
}

#define CP16(smem_addr, gptr) \
    asm volatile("cp.async.cg.shared.global [%0], [%1], 16;" \
        :: "r"(smem_addr), "l"(gptr) : "memory")
#define CP_COMMIT() asm volatile("cp.async.commit_group;" ::: "memory")
#define CP_WAIT2()  asm volatile("cp.async.wait_group 2;" ::: "memory")

#define LDSM4(r0, r1, r2, r3, addr) \
    asm volatile("ldmatrix.sync.aligned.m8n8.x4.shared.b16 {%0,%1,%2,%3}, [%4];" \
        : "=r"(r0), "=r"(r1), "=r"(r2), "=r"(r3) : "r"(addr))

#define MMA16816H(d, a, b) \
    asm volatile("mma.sync.aligned.m16n8k16.row.col.f32.f16.f16.f32 " \
        "{%0,%1,%2,%3},{%4,%5,%6,%7},{%8,%9},{%0,%1,%2,%3};" \
        : "+f"((d)[0]), "+f"((d)[1]), "+f"((d)[2]), "+f"((d)[3]) \
        : "r"((a)[0]), "r"((a)[1]), "r"((a)[2]), "r"((a)[3]), \
          "r"((b)[0]), "r"((b)[1]))

// ---------------------------------------------------------------------------
// k_zero: zero g_deg (must precede k_prep's hist blocks)
// ---------------------------------------------------------------------------
__global__ void k_zero() {
    int i = blockIdx.x * blockDim.x + threadIdx.x;
    if (i < NN) g_deg[i] = 0;
}

// ---------------------------------------------------------------------------
// k_prep: fused degree-hist + W->fp16 transpose + x->fp16 convert.
// blocks [0,1563): hist chunks (1024 edges each);
// [1563,2331): wconv; [2331,27331): xconv
// ---------------------------------------------------------------------------
__global__ void __launch_bounds__(256) k_prep(const int* __restrict__ ei,
                                             const float* __restrict__ x,
                                             const float* __restrict__ W1,
                                             const float* __restrict__ W2,
                                             const float* __restrict__ W3) {
    int bid = blockIdx.x;
    if (bid < 1563) {
        int base = bid * 1024 + threadIdx.x;
        #pragma unroll
        for (int it = 0; it < 4; it++) {
            int e = base + it * 256;
            if (e < EE) atomicAdd(&g_deg[ei[EE + e]], 1);
        }
    } else if (bid < 2331) {
        int idx = (bid - 1563) * 256 + threadIdx.x;   // 0..196607
        int l = idx >> 16;
        int r = idx & 65535;
        int k = r >> 8, n = r & 255;
        const float* W = (l == 0) ? W1 : ((l == 1) ? W2 : W3);
        g_wf[l * 65536 + n * 256 + k] = __float2half_rn(W[k * 256 + n]);
    } else {
        size_t i = (size_t)(bid - 2331) * 256 + threadIdx.x;   // float4 index
        if (i < (size_t)NN * 64) {
            float4 v = ((const float4*)x)[i];
            uint2 h;
            *(__half2*)&h.x = __floats2half2_rn(v.x, v.y);
            *(__half2*)&h.y = __floats2half2_rn(v.z, v.w);
            *(uint2*)(g_act + i * 4) = h;
        }
    }
}

// ---------------------------------------------------------------------------
// Scan chain + scatter
// ---------------------------------------------------------------------------
__global__ void k_scan1() {
    __shared__ int sh[1024];
    int i = blockIdx.x * 1024 + threadIdx.x;
    int v = (i < NN) ? g_deg[i] : 0;
    if (i < NN) g_dinv[i] = rsqrtf((float)v + 1.0f);
    sh[threadIdx.x] = v;
    __syncthreads();
    #pragma unroll
    for (int off = 1; off < 1024; off <<= 1) {
        int t = (threadIdx.x >= off) ? sh[threadIdx.x - off] : 0;
        __syncthreads();
        sh[threadIdx.x] += t;
        __syncthreads();
    }
    if (i < NN) g_rowptr[i] = sh[threadIdx.x] - v;
    if (threadIdx.x == 1023) g_bsum[blockIdx.x] = sh[1023];
}

__global__ void k_scan2() {
    __shared__ int sh[128];
    const int NB = (NN + 1023) / 1024;
    int v = (threadIdx.x < NB) ? g_bsum[threadIdx.x] : 0;
    sh[threadIdx.x] = v;
    __syncthreads();
    #pragma unroll
    for (int off = 1; off < 128; off <<= 1) {
        int t = (threadIdx.x >= off) ? sh[threadIdx.x - off] : 0;
        __syncthreads();
        sh[threadIdx.x] += t;
        __syncthreads();
    }
    g_bsum[threadIdx.x] = sh[threadIdx.x] - v;
}

__global__ void k_scan3() {
    int i = blockIdx.x * 1024 + threadIdx.x;
    if (i < NN) {
        g_rowptr[i] += g_bsum[blockIdx.x];
        g_cursor[i] = 0;
    }
    if (i == 0) g_rowptr[NN] = EE;
}

__global__ void k_scatter(const int* __restrict__ ei) {
    int e = blockIdx.x * blockDim.x + threadIdx.x;
    if (e >= EE) return;
    int s = ei[e];
    int d = ei[EE + e];
    int pos = g_rowptr[d] + atomicAdd(&g_cursor[d], 1);
    g_edges[pos] = make_int2(s, __float_as_int(g_dinv[s] * g_dinv[d]));
}

// ---------------------------------------------------------------------------
// fp16 tensor GEMM via mma.sync:
//   g_gh[M x 256] (fp16) = g_act[M x 256] (fp16) @ W[256 x 256] (fp16)
// CTA tile 128x128, 8 warps (4m x 2n), warp tile 32x64, K-step 16.
// 4-stage cp.async ring, one barrier/K-step. Grid (2, 782).
// ---------------------------------------------------------------------------
#define MG_STAGE 12288u
#define MG_SMEM  49152

__global__ void __launch_bounds__(256, 2) k_mgemm(int lidx) {
    extern __shared__ char smem[];
    const uint32_t sb = smem_u32(smem);

    const int tid  = threadIdx.x;
    const int wid  = tid >> 5;
    const int lane = tid & 31;
    const int wm   = wid >> 1;          // 0..3
    const int wn   = wid & 1;           // 0..1
    const int    ncol0 = blockIdx.x * 128;
    const size_t row0  = (size_t)blockIdx.y * 128;

    const __half* __restrict__ Wf = g_wf + (size_t)lidx * 65536;

    const int gr = tid >> 1;            // 0..127 (row / ncol)
    const int gk = (tid & 1) * 8;       // fp16 k offset within 16
    const size_t gA = (row0 + gr) * 256 + gk;
    const size_t gB = ((size_t)(ncol0 + gr)) * 256 + gk;
    const uint32_t sOff = (uint32_t)(gr * 48 + gk * 2);

    const int lr = lane & 7;
    const uint32_t offA = (uint32_t)((wm * 32 + lr + ((lane >> 3) & 1) * 8) * 48
                                     + ((lane >> 4) & 1) * 16);
    const uint32_t offB = (uint32_t)((wn * 64 + lr + ((lane >> 4) & 1) * 8) * 48
                                     + ((lane >> 3) & 1) * 16);

    float acc[2][8][4];
    #pragma unroll
    for (int i = 0; i < 2; i++)
        #pragma unroll
        for (int j = 0; j < 8; j++)
            #pragma unroll
            for (int q = 0; q < 4; q++) acc[i][j][q] = 0.f;

    #pragma unroll
    for (int p = 0; p < 3; p++) {
        const uint32_t bo = (uint32_t)p * MG_STAGE;
        const size_t kk = (size_t)p * 16;
        CP16(sb + bo + sOff,         g_act + gA + kk);
        CP16(sb + bo + 6144u + sOff, Wf + gB + kk);
        CP_COMMIT();
    }

    for (int c = 0; c < 16; c++) {
        CP_WAIT2();
        __syncthreads();

        if (c + 3 < 16) {
            const uint32_t bo = (uint32_t)((c + 3) & 3) * MG_STAGE;
            const size_t kk = (size_t)(c + 3) * 16;
            CP16(sb + bo + sOff,         g_act + gA + kk);
            CP16(sb + bo + 6144u + sOff, Wf + gB + kk);
        }
        CP_COMMIT();

        const uint32_t base  = sb + (uint32_t)(c & 3) * MG_STAGE;
        const uint32_t aBase = base + offA;
        const uint32_t bBase = base + 6144u + offB;

        uint32_t ah[2][4], bh[8][2];
        #pragma unroll
        for (int mi = 0; mi < 2; mi++)
            LDSM4(ah[mi][0], ah[mi][1], ah[mi][2], ah[mi][3], aBase + mi * 768u);
        #pragma unroll
        for (int j = 0; j < 4; j++) {
            uint32_t t0, t1, t2, t3;
            LDSM4(t0, t1, t2, t3, bBase + j * 768u);
            bh[2 * j][0] = t0; bh[2 * j][1] = t1;
            bh[2 * j + 1][0] = t2; bh[2 * j + 1][1] = t3;
        }

        #pragma unroll
        for (int mi = 0; mi < 2; mi++)
            #pragma unroll
            for (int nj = 0; nj < 8; nj++)
                MMA16816H(acc[mi][nj], ah[mi], bh[nj]);
    }

    // epilogue: write fp16
    #pragma unroll
    for (int mi = 0; mi < 2; mi++) {
        const size_t r0 = row0 + wm * 32 + mi * 16 + (lane >> 2);
        const int cc0 = ncol0 + wn * 64 + (lane & 3) * 2;
        #pragma unroll
        for (int nj = 0; nj < 8; nj++) {
            const int cc = cc0 + nj * 8;
            if (r0 < NN)
                *(__half2*)&g_gh[r0 * 256 + cc] =
                    __floats2half2_rn(acc[mi][nj][0], acc[mi][nj][1]);
            if (r0 + 8 < NN)
                *(__half2*)&g_gh[(r0 + 8) * 256 + cc] =
                    __floats2half2_rn(acc[mi][nj][2], acc[mi][nj][3]);
        }
    }
}

// ---------------------------------------------------------------------------
// Pair-split SpMM gather: each node is handled by TWO warps (warp pair).
// Warp h in {0,1} takes a contiguous half of the edge list; partials are
// combined through smem. Lane covers feats [8l..8l+7] (one uint4/edge).
// Returns true (for warps with h==0 and a valid node) with final acc
// (self-loop + bias + relu applied).
// ---------------------------------------------------------------------------
__device__ __forceinline__ void acc8(float* acc, uint4 v, float w) {
    float2 f0 = __half22float2(*(__half2*)&v.x);
    float2 f1 = __half22float2(*(__half2*)&v.y);
    float2 f2 = __half22float2(*(__half2*)&v.z);
    float2 f3 = __half22float2(*(__half2*)&v.w);
    acc[0] += w * f0.x; acc[1] += w * f0.y;
    acc[2] += w * f1.x; acc[3] += w * f1.y;
    acc[4] += w * f2.x; acc[5] += w * f2.y;
    acc[6] += w * f3.x; acc[7] += w * f3.y;
}

// smem layout: sh[pair][i][lane] (4 pairs, 8 feats, 32 lanes) = 4 KB
struct SpmmShared { float sh[4][8][32]; };

// Performs gather for `node` (may be >= NN: degenerates to no work).
// After this returns, warps with h==0 hold the final row in acc.
__device__ __forceinline__ void spmm_gather_pair(
    SpmmShared* s, int node, int pair, int h, int lane,
    const float* __restrict__ bias, float* acc)
{
    const __half* __restrict__ H = g_gh;

    int beg = 0, end = 0;
    if (node < NN) { beg = g_rowptr[node]; end = g_rowptr[node + 1]; }
    int len  = end - beg;
    int half = (len + 1) >> 1;
    int e0 = beg + h * half;
    int e1 = (h == 0) ? (beg + half) : end;

    #pragma unroll
    for (int i = 0; i < 8; i++) acc[i] = 0.f;

    int e = e0;
    for (; e + 1 < e1; e += 2) {
        int2 p0 = g_edges[e];
        int2 p1 = g_edges[e + 1];
        uint4 v0 = *((const uint4*)(H + (size_t)p0.x * 256) + lane);
        uint4 v1 = *((const uint4*)(H + (size_t)p1.x * 256) + lane);
        acc8(acc, v0, __int_as_float(p0.y));
        acc8(acc, v1, __int_as_float(p1.y));
    }
    for (; e < e1; e++) {
        int2 p = g_edges[e];
        uint4 v = *((const uint4*)(H + (size_t)p.x * 256) + lane);
        acc8(acc, v, __int_as_float(p.y));
    }

    // warp 1 publishes its partial
    if (h == 1) {
        #pragma unroll
        for (int i = 0; i < 8; i++) s->sh[pair][i][lane] = acc[i];
    }
    __syncthreads();

    if (h == 0 && node < NN) {
        #pragma unroll
        for (int i = 0; i < 8; i++) acc[i] += s->sh[pair][i][lane];

        // self-loop
        float di = g_dinv[node];
        uint4 v = *((const uint4*)(H + (size_t)node * 256) + lane);
        acc8(acc, v, di * di);

        // bias + relu
        const float4* bb = (const float4*)bias;
        float4 b0 = bb[2 * lane];
        float4 b1 = bb[2 * lane + 1];
        acc[0] = fmaxf(acc[0] + b0.x, 0.f); acc[1] = fmaxf(acc[1] + b0.y, 0.f);
        acc[2] = fmaxf(acc[2] + b0.z, 0.f); acc[3] = fmaxf(acc[3] + b0.w, 0.f);
        acc[4] = fmaxf(acc[4] + b1.x, 0.f); acc[5] = fmaxf(acc[5] + b1.y, 0.f);
        acc[6] = fmaxf(acc[6] + b1.z, 0.f); acc[7] = fmaxf(acc[7] + b1.w, 0.f);
    }
}

// ---------------------------------------------------------------------------
// SpMM (F=256), layers 1,2: 4 nodes/block (2 warps per node); fp16 out.
// ---------------------------------------------------------------------------
__global__ void __launch_bounds__(256) k_spmm256(const float* __restrict__ bias) {
    __shared__ SpmmShared s;
    int warp = threadIdx.x >> 5;
    int lane = threadIdx.x & 31;
    int pair = warp >> 1;
    int h    = warp & 1;
    int node = blockIdx.x * 4 + pair;

    float acc[8];
    spmm_gather_pair(&s, node, pair, h, lane, bias, acc);

    if (h == 0 && node < NN) {
        uint4 o;
        *(__half2*)&o.x = __floats2half2_rn(acc[0], acc[1]);
        *(__half2*)&o.y = __floats2half2_rn(acc[2], acc[3]);
        *(__half2*)&o.z = __floats2half2_rn(acc[4], acc[5]);
        *(__half2*)&o.w = __floats2half2_rn(acc[6], acc[7]);
        *((uint4*)(g_act + (size_t)node * 256) + lane) = o;
    }
}

// ---------------------------------------------------------------------------
// Layer-3 SpMM fused with the layer-4 linear: h4 = relu(agg3 + b3) @ W4.
// Pair-split gather, then warp-0 of each pair does the W4 dot + butterfly.
// ---------------------------------------------------------------------------
__global__ void __launch_bounds__(256) k_spmm256_w4(const float* __restrict__ bias,
                                                   const float* __restrict__ W4) {
    __shared__ SpmmShared s;
    __shared__ float Ws[16 * 264];   // Ws[c*264 + k] = W4[k*16 + c]
    for (int idx = threadIdx.x; idx < 4096; idx += 256) {
        int k = idx >> 4, c = idx & 15;
        Ws[c * 264 + k] = W4[idx];
    }
    __syncthreads();

    int warp = threadIdx.x >> 5;
    int lane = threadIdx.x & 31;
    int pair = warp >> 1;
    int h    = warp & 1;
    int node = blockIdx.x * 4 + pair;

    float acc[8];
    spmm_gather_pair(&s, node, pair, h, lane, bias, acc);

    if (h == 0) {
        float p[16];
        #pragma unroll
        for (int c = 0; c < 16; c++) {
            float4 w0 = *(const float4*)&Ws[c * 264 + 8 * lane];
            float4 w1 = *(const float4*)&Ws[c * 264 + 8 * lane + 4];
            p[c] = acc[0] * w0.x + acc[1] * w0.y + acc[2] * w0.z + acc[3] * w0.w
                 + acc[4] * w1.x + acc[5] * w1.y + acc[6] * w1.z + acc[7] * w1.w;
        }
        #pragma unroll
        for (int off = 16; off > 0; off >>= 1)
            #pragma unroll
            for (int c = 0; c < 16; c++)
                p[c] += __shfl_xor_sync(0xffffffffu, p[c], off);

        if (node < NN && lane < 16)
            g_h4[(size_t)node * 16 + lane] = p[lane];
    }
}

// ---------------------------------------------------------------------------
// SpMM (F=16) + bias + log_softmax -> final output (reads g_h4, fp32)
// ---------------------------------------------------------------------------
__global__ void __launch_bounds__(256) k_spmm16(const float* __restrict__ bias,
                                               float* __restrict__ out) {
    const float* __restrict__ H = g_h4;

    int warp = threadIdx.x >> 5;
    int lane = threadIdx.x & 31;
    int node = blockIdx.x * 8 + warp;
    if (node >= NN) return;

    int f = lane & 15;
    int beg = g_rowptr[node];
    int end = g_rowptr[node + 1];

    float acc = 0.f;
    for (int e = beg; e < end; e++) {
        int2 p = g_edges[e];
        acc += __int_as_float(p.y) * H[(size_t)p.x * 16 + f];
    }
    float di = g_dinv[node];
    acc += di * di * H[(size_t)node * 16 + f];
    acc += bias[f];

    float m = acc;
    #pragma unroll
    for (int o = 8; o > 0; o >>= 1)
        m = fmaxf(m, __shfl_xor_sync(0xffffffffu, m, o, 16));
    float ex = expf(acc - m);
    float s = ex;
    #pragma unroll
    for (int o = 8; o > 0; o >>= 1)
        s += __shfl_xor_sync(0xffffffffu, s, o, 16);

    if (lane < 16)
        out[(size_t)node * 16 + f] = (acc - m) - logf(s);
}

// ---------------------------------------------------------------------------
// Launcher — single stream
// ---------------------------------------------------------------------------
extern "C" void kernel_launch(void* const* d_in, const int* in_sizes, int n_in,
                              void* d_out, int out_size)
{
    const float* x  = (const float*)d_in[0];
    const int*   ei = (const int*)  d_in[1];
    const float* W1 = (const float*)d_in[2];
    const float* b1 = (const float*)d_in[3];
    const float* W2 = (const float*)d_in[4];
    const float* b2 = (const float*)d_in[5];
    const float* W3 = (const float*)d_in[6];
    const float* b3 = (const float*)d_in[7];
    const float* W4 = (const float*)d_in[8];
    const float* b4 = (const float*)d_in[9];
    float* out = (float*)d_out;

    static int s_attr_done = 0;
    if (!s_attr_done) {
        cudaFuncSetAttribute(k_mgemm, cudaFuncAttributeMaxDynamicSharedMemorySize, MG_SMEM);
        s_attr_done = 1;
    }

    const int NB_SCAN = (NN + 1023) / 1024;   // 98
    const int sgrid  = (NN + 3) / 4;          // 25000 (pair-split SpMM)
    const int sgrid8 = (NN + 7) / 8;          // 12500 (k_spmm16)

    // zero g_deg (kernel boundary orders it before k_prep's hist blocks)
    k_zero   <<<(NN + 255) / 256, 256>>>();
    // prep: hist + W->fp16 + x->fp16 (independent blocks, one kernel)
    k_prep   <<<27331, 256>>>(ei, x, W1, W2, W3);

    // CSR build
    k_scan1  <<<NB_SCAN, 1024>>>();
    k_scan2  <<<1, 128>>>();
    k_scan3  <<<NB_SCAN, 1024>>>();
    k_scatter<<<(EE + 255) / 256, 256>>>(ei);

    dim3 ggrid(2, MPAD / 128);                // N-split fastest (L2 reuse of A)

    // layer 1
    k_mgemm  <<<ggrid, 256, MG_SMEM>>>(0);
    k_spmm256<<<sgrid, 256>>>(b1);
    // layer 2
    k_mgemm  <<<ggrid, 256, MG_SMEM>>>(1);
    k_spmm256<<<sgrid, 256>>>(b2);
    // layer 3 (+ fused layer-4 linear)
    k_mgemm  <<<ggrid, 256, MG_SMEM>>>(2);
    k_spmm256_w4<<<sgrid, 256>>>(b3, W4);
    // layer 4 aggregate + log_softmax
    k_spmm16 <<<sgrid8, 256>>>(b4, out);
}

// round 14
// speedup vs baseline: 1.1049x; 1.1049x over previous
#include <cuda_runtime.h>
#include <cuda_bf16.h>
#include <cuda_fp16.h>
#include <math.h>
#include <stdint.h>

// Problem constants (fixed by reference)
#define NN   100000
#define EE   1600000
#define MPAD 100096   // 782 * 128

// ---------------------------------------------------------------------------
// Scratch (__device__ globals; no runtime allocation)
// ---------------------------------------------------------------------------
__device__ __half g_gh[(size_t)MPAD * 256];    // GEMM output (fp16) / SpMM gather input
__device__ __half g_act[(size_t)MPAD * 256];   // activations (fp16) / GEMM A input
__device__ __half g_wf[3 * 256 * 256];         // W^T per layer (n-major, k contig, fp16)
__device__ float  g_h4[(size_t)NN * 16];       // fused layer-4 pre-agg (fp32)
__device__ int    g_deg[NN];
__device__ float  g_dinv[NN];
__device__ int    g_rowptr[NN + 1];
__device__ int    g_cursor[NN];
__device__ int    g_bsum[128];
__device__ int2   g_edges[EE];                 // packed (src, norm-bits)

// ---------------------------------------------------------------------------
// PTX helpers (sm_80-era; valid on plain compute_100 target)
// ---------------------------------------------------------------------------
__device__ __forceinline__ uint32_t smem_u32(const void* p) {
    uint32_t a;
    asm("{ .reg .u64 t; cvta.to.shared.u64 t, %1; cvt.u32.u64 %0, t; }"
        : "=r"(a) : "l"(p));
    return a;
}

#define CP16(smem_addr, gptr) \
    asm volatile("cp.async.cg.shared.global [%0], [%1], 16;" \
        :: "r"(smem_addr), "l"(gptr) : "memory")
#define CP_COMMIT() asm volatile("cp.async.commit_group;" ::: "memory")
#define CP_WAIT2()  asm volatile("cp.async.wait_group 2;" ::: "memory")

#define LDSM4(r0, r1, r2, r3, addr) \
    asm volatile("ldmatrix.sync.aligned.m8n8.x4.shared.b16 {%0,%1,%2,%3}, [%4];" \
        : "=r"(r0), "=r"(r1), "=r"(r2), "=r"(r3) : "r"(addr))

// fp16-accumulator HMMA: D(f16x2 x2) = A(f16) * B(f16) + D
#define MMA16816HH(d, a, b) \
    asm volatile("mma.sync.aligned.m16n8k16.row.col.f16.f16.f16.f16 " \
        "{%0,%1},{%2,%3,%4,%5},{%6,%7},{%0,%1};" \
        : "+r"((d)[0]), "+r"((d)[1]) \
        : "r"((a)[0]), "r"((a)[1]), "r"((a)[2]), "r"((a)[3]), \
          "r"((b)[0]), "r"((b)[1]))

// ---------------------------------------------------------------------------
// k_prep: fused zero(g_deg) + W->fp16 transpose + x->fp16 convert
// blocks [0,391): zero; [391,1159): wconv; [1159,26159): xconv
// ---------------------------------------------------------------------------
__global__ void __launch_bounds__(256) k_prep(const float* __restrict__ x,
                                             const float* __restrict__ W1,
                                             const float* __restrict__ W2,
                                             const float* __restrict__ W3) {
    int bid = blockIdx.x;
    if (bid < 391) {
        int i = bid * 256 + threadIdx.x;
        if (i < NN) g_deg[i] = 0;
    } else if (bid < 1159) {
        int idx = (bid - 391) * 256 + threadIdx.x;   // 0..196607
        int l = idx >> 16;
        int r = idx & 65535;
        int k = r >> 8, n = r & 255;
        const float* W = (l == 0) ? W1 : ((l == 1) ? W2 : W3);
        g_wf[l * 65536 + n * 256 + k] = __float2half_rn(W[k * 256 + n]);
    } else {
        size_t i = (size_t)(bid - 1159) * 256 + threadIdx.x;   // float4 index
        if (i < (size_t)NN * 64) {
            float4 v = ((const float4*)x)[i];
            uint2 h;
            *(__half2*)&h.x = __floats2half2_rn(v.x, v.y);
            *(__half2*)&h.y = __floats2half2_rn(v.z, v.w);
            *(uint2*)(g_act + i * 4) = h;
        }
    }
}

// ---------------------------------------------------------------------------
// Graph preprocessing
// ---------------------------------------------------------------------------
__global__ void k_hist(const int* __restrict__ ei) {
    int e = blockIdx.x * blockDim.x + threadIdx.x;
    if (e < EE) atomicAdd(&g_deg[ei[EE + e]], 1);
}

__global__ void k_scan1() {
    __shared__ int sh[1024];
    int i = blockIdx.x * 1024 + threadIdx.x;
    int v = (i < NN) ? g_deg[i] : 0;
    if (i < NN) g_dinv[i] = rsqrtf((float)v + 1.0f);
    sh[threadIdx.x] = v;
    __syncthreads();
    #pragma unroll
    for (int off = 1; off < 1024; off <<= 1) {
        int t = (threadIdx.x >= off) ? sh[threadIdx.x - off] : 0;
        __syncthreads();
        sh[threadIdx.x] += t;
        __syncthreads();
    }
    if (i < NN) g_rowptr[i] = sh[threadIdx.x] - v;
    if (threadIdx.x == 1023) g_bsum[blockIdx.x] = sh[1023];
}

__global__ void k_scan2() {
    __shared__ int sh[128];
    const int NB = (NN + 1023) / 1024;
    int v = (threadIdx.x < NB) ? g_bsum[threadIdx.x] : 0;
    sh[threadIdx.x] = v;
    __syncthreads();
    #pragma unroll
    for (int off = 1; off < 128; off <<= 1) {
        int t = (threadIdx.x >= off) ? sh[threadIdx.x - off] : 0;
        __syncthreads();
        sh[threadIdx.x] += t;
        __syncthreads();
    }
    g_bsum[threadIdx.x] = sh[threadIdx.x] - v;
}

__global__ void k_scan3() {
    int i = blockIdx.x * 1024 + threadIdx.x;
    if (i < NN) {
        g_rowptr[i] += g_bsum[blockIdx.x];
        g_cursor[i] = 0;
    }
    if (i == 0) g_rowptr[NN] = EE;
}

__global__ void k_scatter(const int* __restrict__ ei) {
    int e = blockIdx.x * blockDim.x + threadIdx.x;
    if (e >= EE) return;
    int s = ei[e];
    int d = ei[EE + e];
    int pos = g_rowptr[d] + atomicAdd(&g_cursor[d], 1);
    g_edges[pos] = make_int2(s, __float_as_int(g_dinv[s] * g_dinv[d]));
}

// ---------------------------------------------------------------------------
// fp16 tensor GEMM via mma.sync with fp16 accumulators + chunked fp32
// promotion (every 4 K-steps = K=64):
//   g_gh[M x 256] (fp16) = g_act[M x 256] (fp16) @ W[256 x 256] (fp16)
// CTA tile 128x128, 8 warps (4m x 2n), warp tile 32x64, K-step 16.
// 4-stage cp.async ring, one barrier/K-step. Grid (2, 782).
// ---------------------------------------------------------------------------
#define MG_STAGE 12288u
#define MG_SMEM  49152

__global__ void __launch_bounds__(256, 2) k_mgemm(int lidx) {
    extern __shared__ char smem[];
    const uint32_t sb = smem_u32(smem);

    const int tid  = threadIdx.x;
    const int wid  = tid >> 5;
    const int lane = tid & 31;
    const int wm   = wid >> 1;          // 0..3
    const int wn   = wid & 1;           // 0..1
    const int    ncol0 = blockIdx.x * 128;
    const size_t row0  = (size_t)blockIdx.y * 128;

    const __half* __restrict__ Wf = g_wf + (size_t)lidx * 65536;

    const int gr = tid >> 1;            // 0..127 (row / ncol)
    const int gk = (tid & 1) * 8;       // fp16 k offset within 16
    const size_t gA = (row0 + gr) * 256 + gk;
    const size_t gB = ((size_t)(ncol0 + gr)) * 256 + gk;
    const uint32_t sOff = (uint32_t)(gr * 48 + gk * 2);

    const int lr = lane & 7;
    const uint32_t offA = (uint32_t)((wm * 32 + lr + ((lane >> 3) & 1) * 8) * 48
                                     + ((lane >> 4) & 1) * 16);
    const uint32_t offB = (uint32_t)((wn * 64 + lr + ((lane >> 4) & 1) * 8) * 48
                                     + ((lane >> 3) & 1) * 16);

    float acc[2][8][4];           // fp32 master accumulators
    uint32_t accd[2][8][2];       // fp16x2 chunk accumulators
    #pragma unroll
    for (int i = 0; i < 2; i++)
        #pragma unroll
        for (int j = 0; j < 8; j++)
            #pragma unroll
            for (int q = 0; q < 4; q++) acc[i][j][q] = 0.f;

    #pragma unroll
    for (int p = 0; p < 3; p++) {
        const uint32_t bo = (uint32_t)p * MG_STAGE;
        const size_t kk = (size_t)p * 16;
        CP16(sb + bo + sOff,         g_act + gA + kk);
        CP16(sb + bo + 6144u + sOff, Wf + gB + kk);
        CP_COMMIT();
    }

    for (int c = 0; c < 16; c++) {
        CP_WAIT2();
        __syncthreads();

        if (c + 3 < 16) {
            const uint32_t bo = (uint32_t)((c + 3) & 3) * MG_STAGE;
            const size_t kk = (size_t)(c + 3) * 16;
            CP16(sb + bo + sOff,         g_act + gA + kk);
            CP16(sb + bo + 6144u + sOff, Wf + gB + kk);
        }
        CP_COMMIT();

        const uint32_t base  = sb + (uint32_t)(c & 3) * MG_STAGE;
        const uint32_t aBase = base + offA;
        const uint32_t bBase = base + 6144u + offB;

        uint32_t ah[2][4], bh[8][2];
        #pragma unroll
        for (int mi = 0; mi < 2; mi++)
            LDSM4(ah[mi][0], ah[mi][1], ah[mi][2], ah[mi][3], aBase + mi * 768u);
        #pragma unroll
        for (int j = 0; j < 4; j++) {
            uint32_t t0, t1, t2, t3;
            LDSM4(t0, t1, t2, t3, bBase + j * 768u);
            bh[2 * j][0] = t0; bh[2 * j][1] = t1;
            bh[2 * j + 1][0] = t2; bh[2 * j + 1][1] = t3;
        }

        if ((c & 3) == 0) {
            #pragma unroll
            for (int mi = 0; mi < 2; mi++)
                #pragma unroll
                for (int nj = 0; nj < 8; nj++) {
                    accd[mi][nj][0] = 0u;
                    accd[mi][nj][1] = 0u;
                }
        }

        #pragma unroll
        for (int mi = 0; mi < 2; mi++)
            #pragma unroll
            for (int nj = 0; nj < 8; nj++)
                MMA16816HH(accd[mi][nj], ah[mi], bh[nj]);

        if ((c & 3) == 3) {
            #pragma unroll
            for (int mi = 0; mi < 2; mi++)
                #pragma unroll
                for (int nj = 0; nj < 8; nj++) {
                    float2 f0 = __half22float2(*(__half2*)&accd[mi][nj][0]);
                    float2 f1 = __half22float2(*(__half2*)&accd[mi][nj][1]);
                    acc[mi][nj][0] += f0.x; acc[mi][nj][1] += f0.y;
                    acc[mi][nj][2] += f1.x; acc[mi][nj][3] += f1.y;
                }
        }
    }

    // epilogue: write fp16
    #pragma unroll
    for (int mi = 0; mi < 2; mi++) {
        const size_t r0 = row0 + wm * 32 + mi * 16 + (lane >> 2);
        const int cc0 = ncol0 + wn * 64 + (lane & 3) * 2;
        #pragma unroll
        for (int nj = 0; nj < 8; nj++) {
            const int cc = cc0 + nj * 8;
            if (r0 < NN)
                *(__half2*)&g_gh[r0 * 256 + cc] =
                    __floats2half2_rn(acc[mi][nj][0], acc[mi][nj][1]);
            if (r0 + 8 < NN)
                *(__half2*)&g_gh[(r0 + 8) * 256 + cc] =
                    __floats2half2_rn(acc[mi][nj][2], acc[mi][nj][3]);
        }
    }
}

// ---------------------------------------------------------------------------
// Shared SpMM gather over fp16 rows: lane covers feats [8l..8l+7] via one
// uint4 (16 B) per edge row. Self-loop + bias + relu applied.
// ---------------------------------------------------------------------------
__device__ __forceinline__ void acc8(float* acc, uint4 v, float w) {
    float2 f0 = __half22float2(*(__half2*)&v.x);
    float2 f1 = __half22float2(*(__half2*)&v.y);
    float2 f2 = __half22float2(*(__half2*)&v.z);
    float2 f3 = __half22float2(*(__half2*)&v.w);
    acc[0] += w * f0.x; acc[1] += w * f0.y;
    acc[2] += w * f1.x; acc[3] += w * f1.y;
    acc[4] += w * f2.x; acc[5] += w * f2.y;
    acc[6] += w * f3.x; acc[7] += w * f3.y;
}

__device__ __forceinline__ void spmm_gather(int node, int lane,
                                            const float* __restrict__ bias,
                                            float* acc) {
    const __half* __restrict__ H = g_gh;
    int beg = g_rowptr[node];
    int end = g_rowptr[node + 1];

    #pragma unroll
    for (int i = 0; i < 8; i++) acc[i] = 0.f;

    int e = beg;
    for (; e + 1 < end; e += 2) {
        int2 p0 = g_edges[e];
        int2 p1 = g_edges[e + 1];
        uint4 v0 = *((const uint4*)(H + (size_t)p0.x * 256) + lane);
        uint4 v1 = *((const uint4*)(H + (size_t)p1.x * 256) + lane);
        acc8(acc, v0, __int_as_float(p0.y));
        acc8(acc, v1, __int_as_float(p1.y));
    }
    for (; e < end; e++) {
        int2 p = g_edges[e];
        uint4 v = *((const uint4*)(H + (size_t)p.x * 256) + lane);
        acc8(acc, v, __int_as_float(p.y));
    }

    // self-loop
    float di = g_dinv[node];
    {
        uint4 v = *((const uint4*)(H + (size_t)node * 256) + lane);
        acc8(acc, v, di * di);
    }

    // bias + relu (lane covers feats 8l..8l+7)
    const float4* bb = (const float4*)bias;
    float4 b0 = bb[2 * lane];
    float4 b1 = bb[2 * lane + 1];
    acc[0] = fmaxf(acc[0] + b0.x, 0.f); acc[1] = fmaxf(acc[1] + b0.y, 0.f);
    acc[2] = fmaxf(acc[2] + b0.z, 0.f); acc[3] = fmaxf(acc[3] + b0.w, 0.f);
    acc[4] = fmaxf(acc[4] + b1.x, 0.f); acc[5] = fmaxf(acc[5] + b1.y, 0.f);
    acc[6] = fmaxf(acc[6] + b1.z, 0.f); acc[7] = fmaxf(acc[7] + b1.w, 0.f);
}

// ---------------------------------------------------------------------------
// SpMM (F=256) for layers 1,2: writes fp16 activations for the next GEMM.
// ---------------------------------------------------------------------------
__global__ void __launch_bounds__(256) k_spmm256(const float* __restrict__ bias) {
    int warp = threadIdx.x >> 5;
    int lane = threadIdx.x & 31;
    int node = blockIdx.x * 8 + warp;
    if (node >= NN) return;

    float acc[8];
    spmm_gather(node, lane, bias, acc);

    uint4 h;
    *(__half2*)&h.x = __floats2half2_rn(acc[0], acc[1]);
    *(__half2*)&h.y = __floats2half2_rn(acc[2], acc[3]);
    *(__half2*)&h.z = __floats2half2_rn(acc[4], acc[5]);
    *(__half2*)&h.w = __floats2half2_rn(acc[6], acc[7]);
    *((uint4*)(g_act + (size_t)node * 256) + lane) = h;
}

// ---------------------------------------------------------------------------
// Layer-3 SpMM fused with the layer-4 linear: h4 = relu(agg3 + b3) @ W4.
// Lane holds feats [8l..8l+7]; W4 k-major in smem (stride 264); butterfly.
// ---------------------------------------------------------------------------
__global__ void __launch_bounds__(256) k_spmm256_w4(const float* __restrict__ bias,
                                                   const float* __restrict__ W4) {
    __shared__ float Ws[16 * 264];   // Ws[c*264 + k] = W4[k*16 + c]
    for (int idx = threadIdx.x; idx < 4096; idx += 256) {
        int k = idx >> 4, c = idx & 15;
        Ws[c * 264 + k] = W4[idx];
    }
    __syncthreads();

    int warp = threadIdx.x >> 5;
    int lane = threadIdx.x & 31;
    int node = blockIdx.x * 8 + warp;
    if (node >= NN) return;

    float acc[8];
    spmm_gather(node, lane, bias, acc);

    float p[16];
    #pragma unroll
    for (int c = 0; c < 16; c++) {
        float4 w0 = *(const float4*)&Ws[c * 264 + 8 * lane];
        float4 w1 = *(const float4*)&Ws[c * 264 + 8 * lane + 4];
        p[c] = acc[0] * w0.x + acc[1] * w0.y + acc[2] * w0.z + acc[3] * w0.w
             + acc[4] * w1.x + acc[5] * w1.y + acc[6] * w1.z + acc[7] * w1.w;
    }
    #pragma unroll
    for (int off = 16; off > 0; off >>= 1)
        #pragma unroll
        for (int c = 0; c < 16; c++)
            p[c] += __shfl_xor_sync(0xffffffffu, p[c], off);

    if (lane < 16)
        g_h4[(size_t)node * 16 + lane] = p[lane];
}

// ---------------------------------------------------------------------------
// SpMM (F=16) + bias + log_softmax -> final output (reads g_h4, fp32)
// ---------------------------------------------------------------------------
__global__ void __launch_bounds__(256) k_spmm16(const float* __restrict__ bias,
                                               float* __restrict__ out) {
    const float* __restrict__ H = g_h4;

    int warp = threadIdx.x >> 5;
    int lane = threadIdx.x & 31;
    int node = blockIdx.x * 8 + warp;
    if (node >= NN) return;

    int f = lane & 15;
    int beg = g_rowptr[node];
    int end = g_rowptr[node + 1];

    float acc = 0.f;
    for (int e = beg; e < end; e++) {
        int2 p = g_edges[e];
        acc += __int_as_float(p.y) * H[(size_t)p.x * 16 + f];
    }
    float di = g_dinv[node];
    acc += di * di * H[(size_t)node * 16 + f];
    acc += bias[f];

    float m = acc;
    #pragma unroll
    for (int o = 8; o > 0; o >>= 1)
        m = fmaxf(m, __shfl_xor_sync(0xffffffffu, m, o, 16));
    float ex = expf(acc - m);
    float s = ex;
    #pragma unroll
    for (int o = 8; o > 0; o >>= 1)
        s += __shfl_xor_sync(0xffffffffu, s, o, 16);

    if (lane < 16)
        out[(size_t)node * 16 + f] = (acc - m) - logf(s);
}

// ---------------------------------------------------------------------------
// Launcher — single stream (r11 structure, known 647.2us baseline)
// ---------------------------------------------------------------------------
extern "C" void kernel_launch(void* const* d_in, const int* in_sizes, int n_in,
                              void* d_out, int out_size)
{
    const float* x  = (const float*)d_in[0];
    const int*   ei = (const int*)  d_in[1];
    const float* W1 = (const float*)d_in[2];
    const float* b1 = (const float*)d_in[3];
    const float* W2 = (const float*)d_in[4];
    const float* b2 = (const float*)d_in[5];
    const float* W3 = (const float*)d_in[6];
    const float* b3 = (const float*)d_in[7];
    const float* W4 = (const float*)d_in[8];
    const float* b4 = (const float*)d_in[9];
    float* out = (float*)d_out;

    static int s_attr_done = 0;
    if (!s_attr_done) {
        cudaFuncSetAttribute(k_mgemm, cudaFuncAttributeMaxDynamicSharedMemorySize, MG_SMEM);
        s_attr_done = 1;
    }

    const int NB_SCAN = (NN + 1023) / 1024;   // 98
    const int sgrid = (NN + 7) / 8;           // 12500

    // prep: zero(g_deg) + W->fp16 + x->fp16 (independent, one kernel)
    k_prep   <<<26159, 256>>>(x, W1, W2, W3);

    // graph preprocessing
    k_hist   <<<(EE + 255) / 256, 256>>>(ei);
    k_scan1  <<<NB_SCAN, 1024>>>();
    k_scan2  <<<1, 128>>>();
    k_scan3  <<<NB_SCAN, 1024>>>();
    k_scatter<<<(EE + 255) / 256, 256>>>(ei);

    dim3 ggrid(2, MPAD / 128);                // N-split fastest (L2 reuse of A)

    // layer 1
    k_mgemm  <<<ggrid, 256, MG_SMEM>>>(0);
    k_spmm256<<<sgrid, 256>>>(b1);
    // layer 2
    k_mgemm  <<<ggrid, 256, MG_SMEM>>>(1);
    k_spmm256<<<sgrid, 256>>>(b2);
    // layer 3 (+ fused layer-4 linear)
    k_mgemm  <<<ggrid, 256, MG_SMEM>>>(2);
    k_spmm256_w4<<<sgrid, 256>>>(b3, W4);
    // layer 4 aggregate + log_softmax
    k_spmm16 <<<sgrid, 256>>>(b4, out);
}

// round 15
// speedup vs baseline: 1.1965x; 1.0829x over previous
#include <cuda_runtime.h>
#include <cuda_bf16.h>
#include <cuda_fp16.h>
#include <math.h>
#include <stdint.h>

// Problem constants (fixed by reference)
#define NN   100000
#define EE   1600000
#define MPAD 100096   // 782 * 128

// ---------------------------------------------------------------------------
// Scratch (__device__ globals; no runtime allocation)
// ---------------------------------------------------------------------------
__device__ __half g_gh[(size_t)MPAD * 256];    // GEMM output (fp16) / SpMM gather input
__device__ __half g_act[(size_t)MPAD * 256];   // activations (fp16) / GEMM A input
__device__ __half g_wf[3 * 256 * 256];         // W^T per layer (n-major, k contig, fp16)
__device__ __half g_h4[(size_t)NN * 16];       // fused layer-4 pre-agg (fp16)
__device__ int    g_deg[NN];
__device__ float  g_dinv[NN];
__device__ int    g_rowptr[NN + 1];
__device__ int    g_cursor[NN];
__device__ int    g_bsum[128];
__device__ int2   g_edges[EE];                 // packed (src, norm-bits)

// ---------------------------------------------------------------------------
// PTX helpers (sm_80-era; valid on plain compute_100 target)
// ---------------------------------------------------------------------------
__device__ __forceinline__ uint32_t smem_u32(const void* p) {
    uint32_t a;
    asm("{ .reg .u64 t; cvta.to.shared.u64 t, %1; cvt.u32.u64 %0, t; }"
        : "=r"(a) : "l"(p));
    return a;
}

#define CP16(smem_addr, gptr) \
    asm volatile("cp.async.cg.shared.global [%0], [%1], 16;" \
        :: "r"(smem_addr), "l"(gptr) : "memory")
#define CP_COMMIT() asm volatile("cp.async.commit_group;" ::: "memory")
#define CP_WAIT2()  asm volatile("cp.async.wait_group 2;" ::: "memory")

#define LDSM4(r0, r1, r2, r3, addr) \
    asm volatile("ldmatrix.sync.aligned.m8n8.x4.shared.b16 {%0,%1,%2,%3}, [%4];" \
        : "=r"(r0), "=r"(r1), "=r"(r2), "=r"(r3) : "r"(addr))

#define MMA16816H(d, a, b) \
    asm volatile("mma.sync.aligned.m16n8k16.row.col.f32.f16.f16.f32 " \
        "{%0,%1,%2,%3},{%4,%5,%6,%7},{%8,%9},{%0,%1,%2,%3};" \
        : "+f"((d)[0]), "+f"((d)[1]), "+f"((d)[2]), "+f"((d)[3]) \
        : "r"((a)[0]), "r"((a)[1]), "r"((a)[2]), "r"((a)[3]), \
          "r"((b)[0]), "r"((b)[1]))

// ---------------------------------------------------------------------------
// k_prep: fused zero(g_deg) + W->fp16 transpose + x->fp16 convert
// blocks [0,391): zero; [391,1159): wconv; [1159,26159): xconv
// ---------------------------------------------------------------------------
__global__ void __launch_bounds__(256) k_prep(const float* __restrict__ x,
                                             const float* __restrict__ W1,
                                             const float* __restrict__ W2,
                                             const float* __restrict__ W3) {
    int bid = blockIdx.x;
    if (bid < 391) {
        int i = bid * 256 + threadIdx.x;
        if (i < NN) g_deg[i] = 0;
    } else if (bid < 1159) {
        int idx = (bid - 391) * 256 + threadIdx.x;   // 0..196607
        int l = idx >> 16;
        int r = idx & 65535;
        int k = r >> 8, n = r & 255;
        const float* W = (l == 0) ? W1 : ((l == 1) ? W2 : W3);
        g_wf[l * 65536 + n * 256 + k] = __float2half_rn(W[k * 256 + n]);
    } else {
        size_t i = (size_t)(bid - 1159) * 256 + threadIdx.x;   // float4 index
        if (i < (size_t)NN * 64) {
            float4 v = ((const float4*)x)[i];
            uint2 h;
            *(__half2*)&h.x = __floats2half2_rn(v.x, v.y);
            *(__half2*)&h.y = __floats2half2_rn(v.z, v.w);
            *(uint2*)(g_act + i * 4) = h;
        }
    }
}

// ---------------------------------------------------------------------------
// Graph preprocessing
// ---------------------------------------------------------------------------
__global__ void k_hist(const int* __restrict__ ei) {
    int e = blockIdx.x * blockDim.x + threadIdx.x;
    if (e < EE) atomicAdd(&g_deg[ei[EE + e]], 1);
}

__global__ void k_scan1() {
    __shared__ int sh[1024];
    int i = blockIdx.x * 1024 + threadIdx.x;
    int v = (i < NN) ? g_deg[i] : 0;
    if (i < NN) g_dinv[i] = rsqrtf((float)v + 1.0f);
    sh[threadIdx.x] = v;
    __syncthreads();
    #pragma unroll
    for (int off = 1; off < 1024; off <<= 1) {
        int t = (threadIdx.x >= off) ? sh[threadIdx.x - off] : 0;
        __syncthreads();
        sh[threadIdx.x] += t;
        __syncthreads();
    }
    if (i < NN) g_rowptr[i] = sh[threadIdx.x] - v;
    if (threadIdx.x == 1023) g_bsum[blockIdx.x] = sh[1023];
}

__global__ void k_scan2() {
    __shared__ int sh[128];
    const int NB = (NN + 1023) / 1024;
    int v = (threadIdx.x < NB) ? g_bsum[threadIdx.x] : 0;
    sh[threadIdx.x] = v;
    __syncthreads();
    #pragma unroll
    for (int off = 1; off < 128; off <<= 1) {
        int t = (threadIdx.x >= off) ? sh[threadIdx.x - off] : 0;
        __syncthreads();
        sh[threadIdx.x] += t;
        __syncthreads();
    }
    g_bsum[threadIdx.x] = sh[threadIdx.x] - v;
}

__global__ void k_scan3() {
    int i = blockIdx.x * 1024 + threadIdx.x;
    if (i < NN) {
        g_rowptr[i] += g_bsum[blockIdx.x];
        g_cursor[i] = 0;
    }
    if (i == 0) g_rowptr[NN] = EE;
}

__global__ void k_scatter(const int* __restrict__ ei) {
    int e = blockIdx.x * blockDim.x + threadIdx.x;
    if (e >= EE) return;
    int s = ei[e];
    int d = ei[EE + e];
    int pos = g_rowptr[d] + atomicAdd(&g_cursor[d], 1);
    g_edges[pos] = make_int2(s, __float_as_int(g_dinv[s] * g_dinv[d]));
}

// ---------------------------------------------------------------------------
// fp16 tensor GEMM via mma.sync (fp32 accumulate):
//   g_gh[M x 256] (fp16) = g_act[M x 256] (fp16) @ W[256 x 256] (fp16)
// CTA tile 128x128, 8 warps (4m x 2n), warp tile 32x64, K-step 16.
// 4-stage cp.async ring, one barrier/K-step. Grid (2, 782).
// ---------------------------------------------------------------------------
#define MG_STAGE 12288u
#define MG_SMEM  49152

__global__ void __launch_bounds__(256, 2) k_mgemm(int lidx) {
    extern __shared__ char smem[];
    const uint32_t sb = smem_u32(smem);

    const int tid  = threadIdx.x;
    const int wid  = tid >> 5;
    const int lane = tid & 31;
    const int wm   = wid >> 1;          // 0..3
    const int wn   = wid & 1;           // 0..1
    const int    ncol0 = blockIdx.x * 128;
    const size_t row0  = (size_t)blockIdx.y * 128;

    const __half* __restrict__ Wf = g_wf + (size_t)lidx * 65536;

    const int gr = tid >> 1;            // 0..127 (row / ncol)
    const int gk = (tid & 1) * 8;       // fp16 k offset within 16
    const size_t gA = (row0 + gr) * 256 + gk;
    const size_t gB = ((size_t)(ncol0 + gr)) * 256 + gk;
    const uint32_t sOff = (uint32_t)(gr * 48 + gk * 2);

    const int lr = lane & 7;
    const uint32_t offA = (uint32_t)((wm * 32 + lr + ((lane >> 3) & 1) * 8) * 48
                                     + ((lane >> 4) & 1) * 16);
    const uint32_t offB = (uint32_t)((wn * 64 + lr + ((lane >> 4) & 1) * 8) * 48
                                     + ((lane >> 3) & 1) * 16);

    float acc[2][8][4];
    #pragma unroll
    for (int i = 0; i < 2; i++)
        #pragma unroll
        for (int j = 0; j < 8; j++)
            #pragma unroll
            for (int q = 0; q < 4; q++) acc[i][j][q] = 0.f;

    #pragma unroll
    for (int p = 0; p < 3; p++) {
        const uint32_t bo = (uint32_t)p * MG_STAGE;
        const size_t kk = (size_t)p * 16;
        CP16(sb + bo + sOff,         g_act + gA + kk);
        CP16(sb + bo + 6144u + sOff, Wf + gB + kk);
        CP_COMMIT();
    }

    for (int c = 0; c < 16; c++) {
        CP_WAIT2();
        __syncthreads();

        if (c + 3 < 16) {
            const uint32_t bo = (uint32_t)((c + 3) & 3) * MG_STAGE;
            const size_t kk = (size_t)(c + 3) * 16;
            CP16(sb + bo + sOff,         g_act + gA + kk);
            CP16(sb + bo + 6144u + sOff, Wf + gB + kk);
        }
        CP_COMMIT();

        const uint32_t base  = sb + (uint32_t)(c & 3) * MG_STAGE;
        const uint32_t aBase = base + offA;
        const uint32_t bBase = base + 6144u + offB;

        uint32_t ah[2][4], bh[8][2];
        #pragma unroll
        for (int mi = 0; mi < 2; mi++)
            LDSM4(ah[mi][0], ah[mi][1], ah[mi][2], ah[mi][3], aBase + mi * 768u);
        #pragma unroll
        for (int j = 0; j < 4; j++) {
            uint32_t t0, t1, t2, t3;
            LDSM4(t0, t1, t2, t3, bBase + j * 768u);
            bh[2 * j][0] = t0; bh[2 * j][1] = t1;
            bh[2 * j + 1][0] = t2; bh[2 * j + 1][1] = t3;
        }

        #pragma unroll
        for (int mi = 0; mi < 2; mi++)
            #pragma unroll
            for (int nj = 0; nj < 8; nj++)
                MMA16816H(acc[mi][nj], ah[mi], bh[nj]);
    }

    // epilogue: write fp16
    #pragma unroll
    for (int mi = 0; mi < 2; mi++) {
        const size_t r0 = row0 + wm * 32 + mi * 16 + (lane >> 2);
        const int cc0 = ncol0 + wn * 64 + (lane & 3) * 2;
        #pragma unroll
        for (int nj = 0; nj < 8; nj++) {
            const int cc = cc0 + nj * 8;
            if (r0 < NN)
                *(__half2*)&g_gh[r0 * 256 + cc] =
                    __floats2half2_rn(acc[mi][nj][0], acc[mi][nj][1]);
            if (r0 + 8 < NN)
                *(__half2*)&g_gh[(r0 + 8) * 256 + cc] =
                    __floats2half2_rn(acc[mi][nj][2], acc[mi][nj][3]);
        }
    }
}

// ---------------------------------------------------------------------------
// Shared SpMM gather over fp16 rows: lane covers feats [8l..8l+7] via one
// uint4 (16 B) per edge row. Self-loop + bias + relu applied.
// ---------------------------------------------------------------------------
__device__ __forceinline__ void acc8(float* acc, uint4 v, float w) {
    float2 f0 = __half22float2(*(__half2*)&v.x);
    float2 f1 = __half22float2(*(__half2*)&v.y);
    float2 f2 = __half22float2(*(__half2*)&v.z);
    float2 f3 = __half22float2(*(__half2*)&v.w);
    acc[0] += w * f0.x; acc[1] += w * f0.y;
    acc[2] += w * f1.x; acc[3] += w * f1.y;
    acc[4] += w * f2.x; acc[5] += w * f2.y;
    acc[6] += w * f3.x; acc[7] += w * f3.y;
}

__device__ __forceinline__ void spmm_gather(int node, int lane,
                                            const float* __restrict__ bias,
                                            float* acc) {
    const __half* __restrict__ H = g_gh;
    int beg = g_rowptr[node];
    int end = g_rowptr[node + 1];

    #pragma unroll
    for (int i = 0; i < 8; i++) acc[i] = 0.f;

    int e = beg;
    for (; e + 1 < end; e += 2) {
        int2 p0 = g_edges[e];
        int2 p1 = g_edges[e + 1];
        uint4 v0 = *((const uint4*)(H + (size_t)p0.x * 256) + lane);
        uint4 v1 = *((const uint4*)(H + (size_t)p1.x * 256) + lane);
        acc8(acc, v0, __int_as_float(p0.y));
        acc8(acc, v1, __int_as_float(p1.y));
    }
    for (; e < end; e++) {
        int2 p = g_edges[e];
        uint4 v = *((const uint4*)(H + (size_t)p.x * 256) + lane);
        acc8(acc, v, __int_as_float(p.y));
    }

    // self-loop
    float di = g_dinv[node];
    {
        uint4 v = *((const uint4*)(H + (size_t)node * 256) + lane);
        acc8(acc, v, di * di);
    }

    // bias + relu (lane covers feats 8l..8l+7)
    const float4* bb = (const float4*)bias;
    float4 b0 = bb[2 * lane];
    float4 b1 = bb[2 * lane + 1];
    acc[0] = fmaxf(acc[0] + b0.x, 0.f); acc[1] = fmaxf(acc[1] + b0.y, 0.f);
    acc[2] = fmaxf(acc[2] + b0.z, 0.f); acc[3] = fmaxf(acc[3] + b0.w, 0.f);
    acc[4] = fmaxf(acc[4] + b1.x, 0.f); acc[5] = fmaxf(acc[5] + b1.y, 0.f);
    acc[6] = fmaxf(acc[6] + b1.z, 0.f); acc[7] = fmaxf(acc[7] + b1.w, 0.f);
}

// ---------------------------------------------------------------------------
// SpMM (F=256) for layers 1,2: writes fp16 activations for the next GEMM.
// ---------------------------------------------------------------------------
__global__ void __launch_bounds__(256) k_spmm256(const float* __restrict__ bias) {
    int warp = threadIdx.x >> 5;
    int lane = threadIdx.x & 31;
    int node = blockIdx.x * 8 + warp;
    if (node >= NN) return;

    float acc[8];
    spmm_gather(node, lane, bias, acc);

    uint4 h;
    *(__half2*)&h.x = __floats2half2_rn(acc[0], acc[1]);
    *(__half2*)&h.y = __floats2half2_rn(acc[2], acc[3]);
    *(__half2*)&h.z = __floats2half2_rn(acc[4], acc[5]);
    *(__half2*)&h.w = __floats2half2_rn(acc[6], acc[7]);
    *((uint4*)(g_act + (size_t)node * 256) + lane) = h;
}

// ---------------------------------------------------------------------------
// Layer-3 SpMM fused with the layer-4 linear: h4 = relu(agg3 + b3) @ W4.
// Lane holds feats [8l..8l+7]; W4 k-major in smem (stride 264); butterfly.
// Writes g_h4 as fp16 (tail gather traffic halved).
// ---------------------------------------------------------------------------
__global__ void __launch_bounds__(256) k_spmm256_w4(const float* __restrict__ bias,
                                                   const float* __restrict__ W4) {
    __shared__ float Ws[16 * 264];   // Ws[c*264 + k] = W4[k*16 + c]
    for (int idx = threadIdx.x; idx < 4096; idx += 256) {
        int k = idx >> 4, c = idx & 15;
        Ws[c * 264 + k] = W4[idx];
    }
    __syncthreads();

    int warp = threadIdx.x >> 5;
    int lane = threadIdx.x & 31;
    int node = blockIdx.x * 8 + warp;
    if (node >= NN) return;

    float acc[8];
    spmm_gather(node, lane, bias, acc);

    float p[16];
    #pragma unroll
    for (int c = 0; c < 16; c++) {
        float4 w0 = *(const float4*)&Ws[c * 264 + 8 * lane];
        float4 w1 = *(const float4*)&Ws[c * 264 + 8 * lane + 4];
        p[c] = acc[0] * w0.x + acc[1] * w0.y + acc[2] * w0.z + acc[3] * w0.w
             + acc[4] * w1.x + acc[5] * w1.y + acc[6] * w1.z + acc[7] * w1.w;
    }
    #pragma unroll
    for (int off = 16; off > 0; off >>= 1)
        #pragma unroll
        for (int c = 0; c < 16; c++)
            p[c] += __shfl_xor_sync(0xffffffffu, p[c], off);

    if (lane < 16)
        g_h4[(size_t)node * 16 + lane] = __float2half_rn(p[lane]);
}

// ---------------------------------------------------------------------------
// SpMM (F=16) + bias + log_softmax -> final output (reads g_h4, fp16)
// ---------------------------------------------------------------------------
__global__ void __launch_bounds__(256) k_spmm16(const float* __restrict__ bias,
                                               float* __restrict__ out) {
    const __half* __restrict__ H = g_h4;

    int warp = threadIdx.x >> 5;
    int lane = threadIdx.x & 31;
    int node = blockIdx.x * 8 + warp;
    if (node >= NN) return;

    int f = lane & 15;
    int beg = g_rowptr[node];
    int end = g_rowptr[node + 1];

    float acc = 0.f;
    for (int e = beg; e < end; e++) {
        int2 p = g_edges[e];
        acc += __int_as_float(p.y) * __half2float(H[(size_t)p.x * 16 + f]);
    }
    float di = g_dinv[node];
    acc += di * di * __half2float(H[(size_t)node * 16 + f]);
    acc += bias[f];

    float m = acc;
    #pragma unroll
    for (int o = 8; o > 0; o >>= 1)
        m = fmaxf(m, __shfl_xor_sync(0xffffffffu, m, o, 16));
    float ex = expf(acc - m);
    float s = ex;
    #pragma unroll
    for (int o = 8; o > 0; o >>= 1)
        s += __shfl_xor_sync(0xffffffffu, s, o, 16);

    if (lane < 16)
        out[(size_t)node * 16 + f] = (acc - m) - logf(s);
}

// ---------------------------------------------------------------------------
// Launcher — single stream (r11 structure; fp16 g_h4 tail)
// ---------------------------------------------------------------------------
extern "C" void kernel_launch(void* const* d_in, const int* in_sizes, int n_in,
                              void* d_out, int out_size)
{
    const float* x  = (const float*)d_in[0];
    const int*   ei = (const int*)  d_in[1];
    const float* W1 = (const float*)d_in[2];
    const float* b1 = (const float*)d_in[3];
    const float* W2 = (const float*)d_in[4];
    const float* b2 = (const float*)d_in[5];
    const float* W3 = (const float*)d_in[6];
    const float* b3 = (const float*)d_in[7];
    const float* W4 = (const float*)d_in[8];
    const float* b4 = (const float*)d_in[9];
    float* out = (float*)d_out;

    static int s_attr_done = 0;
    if (!s_attr_done) {
        cudaFuncSetAttribute(k_mgemm, cudaFuncAttributeMaxDynamicSharedMemorySize, MG_SMEM);
        s_attr_done = 1;
    }

    const int NB_SCAN = (NN + 1023) / 1024;   // 98
    const int sgrid = (NN + 7) / 8;           // 12500

    // prep: zero(g_deg) + W->fp16 + x->fp16 (independent, one kernel)
    k_prep   <<<26159, 256>>>(x, W1, W2, W3);

    // graph preprocessing
    k_hist   <<<(EE + 255) / 256, 256>>>(ei);
    k_scan1  <<<NB_SCAN, 1024>>>();
    k_scan2  <<<1, 128>>>();
    k_scan3  <<<NB_SCAN, 1024>>>();
    k_scatter<<<(EE + 255) / 256, 256>>>(ei);

    dim3 ggrid(2, MPAD / 128);                // N-split fastest (L2 reuse of A)

    // layer 1
    k_mgemm  <<<ggrid, 256, MG_SMEM>>>(0);
    k_spmm256<<<sgrid, 256>>>(b1);
    // layer 2
    k_mgemm  <<<ggrid, 256, MG_SMEM>>>(1);
    k_spmm256<<<sgrid, 256>>>(b2);
    // layer 3 (+ fused layer-4 linear)
    k_mgemm  <<<ggrid, 256, MG_SMEM>>>(2);
    k_spmm256_w4<<<sgrid, 256>>>(b3, W4);
    // layer 4 aggregate + log_softmax
    k_spmm16 <<<sgrid, 256>>>(b4, out);
}

// round 16
// speedup vs baseline: 1.1992x; 1.0023x over previous
#include <cuda_runtime.h>
#include <cuda_bf16.h>
#include <cuda_fp16.h>
#include <math.h>
#include <stdint.h>

// Problem constants (fixed by reference)
#define NN   100000
#define EE   1600000
#define MPAD 100096   // 782 * 128

// ---------------------------------------------------------------------------
// Scratch (__device__ globals; no runtime allocation)
// ---------------------------------------------------------------------------
__device__ __half g_gh[(size_t)MPAD * 256];    // GEMM output (fp16) / SpMM gather input
__device__ __half g_act[(size_t)MPAD * 256];   // activations (fp16) / GEMM A input
__device__ __half g_wf[3 * 256 * 256];         // W^T per layer (n-major, k contig, fp16)
__device__ __half g_h4[(size_t)NN * 16];       // fused layer-4 pre-agg (fp16)
__device__ int    g_deg[NN];
__device__ float  g_dinv[NN];
__device__ int    g_rowptr[NN];                // segment start per node (disjoint)
__device__ int    g_cursor[NN];
__device__ int    g_alloc;                     // global segment allocator
__device__ int2   g_edges[EE];                 // packed (src, norm-bits)

// ---------------------------------------------------------------------------
// PTX helpers (sm_80-era; valid on plain compute_100 target)
// ---------------------------------------------------------------------------
__device__ __forceinline__ uint32_t smem_u32(const void* p) {
    uint32_t a;
    asm("{ .reg .u64 t; cvta.to.shared.u64 t, %1; cvt.u32.u64 %0, t; }"
        : "=r"(a) : "l"(p));
    return a;
}

#define CP16(smem_addr, gptr) \
    asm volatile("cp.async.cg.shared.global [%0], [%1], 16;" \
        :: "r"(smem_addr), "l"(gptr) : "memory")
#define CP_COMMIT() asm volatile("cp.async.commit_group;" ::: "memory")
#define CP_WAIT2()  asm volatile("cp.async.wait_group 2;" ::: "memory")

#define LDSM4(r0, r1, r2, r3, addr) \
    asm volatile("ldmatrix.sync.aligned.m8n8.x4.shared.b16 {%0,%1,%2,%3}, [%4];" \
        : "=r"(r0), "=r"(r1), "=r"(r2), "=r"(r3) : "r"(addr))

#define MMA16816H(d, a, b) \
    asm volatile("mma.sync.aligned.m16n8k16.row.col.f32.f16.f16.f32 " \
        "{%0,%1,%2,%3},{%4,%5,%6,%7},{%8,%9},{%0,%1,%2,%3};" \
        : "+f"((d)[0]), "+f"((d)[1]), "+f"((d)[2]), "+f"((d)[3]) \
        : "r"((a)[0]), "r"((a)[1]), "r"((a)[2]), "r"((a)[3]), \
          "r"((b)[0]), "r"((b)[1]))

// ---------------------------------------------------------------------------
// k_prep: fused zero(g_deg, g_alloc) + W->fp16 transpose + x->fp16 convert
// blocks [0,391): zero; [391,1159): wconv; [1159,26159): xconv
// ---------------------------------------------------------------------------
__global__ void __launch_bounds__(256) k_prep(const float* __restrict__ x,
                                             const float* __restrict__ W1,
                                             const float* __restrict__ W2,
                                             const float* __restrict__ W3) {
    int bid = blockIdx.x;
    if (bid < 391) {
        int i = bid * 256 + threadIdx.x;
        if (i < NN) g_deg[i] = 0;
        if (bid == 0 && threadIdx.x == 0) g_alloc = 0;
    } else if (bid < 1159) {
        int idx = (bid - 391) * 256 + threadIdx.x;   // 0..196607
        int l = idx >> 16;
        int r = idx & 65535;
        int k = r >> 8, n = r & 255;
        const float* W = (l == 0) ? W1 : ((l == 1) ? W2 : W3);
        g_wf[l * 65536 + n * 256 + k] = __float2half_rn(W[k * 256 + n]);
    } else {
        size_t i = (size_t)(bid - 1159) * 256 + threadIdx.x;   // float4 index
        if (i < (size_t)NN * 64) {
            float4 v = ((const float4*)x)[i];
            uint2 h;
            *(__half2*)&h.x = __floats2half2_rn(v.x, v.y);
            *(__half2*)&h.y = __floats2half2_rn(v.z, v.w);
            *(uint2*)(g_act + i * 4) = h;
        }
    }
}

// ---------------------------------------------------------------------------
// Graph preprocessing
// ---------------------------------------------------------------------------
__global__ void k_hist(const int* __restrict__ ei) {
    int e = blockIdx.x * blockDim.x + threadIdx.x;
    if (e < EE) atomicAdd(&g_deg[ei[EE + e]], 1);
}

// Single-kernel CSR offsets: per-block scan of degrees + one global
// atomicAdd per block for the base. Segments are disjoint (order across
// blocks is arbitrary — no consumer needs monotone rowptr).
__global__ void k_csr() {
    __shared__ int sh[1024];
    __shared__ int base;
    int i = blockIdx.x * 1024 + threadIdx.x;
    int v = (i < NN) ? g_deg[i] : 0;
    if (i < NN) {
        g_dinv[i] = rsqrtf((float)v + 1.0f);
        g_cursor[i] = 0;
    }
    sh[threadIdx.x] = v;
    __syncthreads();
    #pragma unroll
    for (int off = 1; off < 1024; off <<= 1) {
        int t = (threadIdx.x >= off) ? sh[threadIdx.x - off] : 0;
        __syncthreads();
        sh[threadIdx.x] += t;
        __syncthreads();
    }
    if (threadIdx.x == 1023) base = atomicAdd(&g_alloc, sh[1023]);
    __syncthreads();
    if (i < NN) g_rowptr[i] = base + sh[threadIdx.x] - v;
}

__global__ void k_scatter(const int* __restrict__ ei) {
    int e = blockIdx.x * blockDim.x + threadIdx.x;
    if (e >= EE) return;
    int s = ei[e];
    int d = ei[EE + e];
    int pos = g_rowptr[d] + atomicAdd(&g_cursor[d], 1);
    g_edges[pos] = make_int2(s, __float_as_int(g_dinv[s] * g_dinv[d]));
}

// ---------------------------------------------------------------------------
// fp16 tensor GEMM via mma.sync (fp32 accumulate):
//   g_gh[M x 256] (fp16) = g_act[M x 256] (fp16) @ W[256 x 256] (fp16)
// CTA tile 128x128, 8 warps (4m x 2n), warp tile 32x64, K-step 16.
// 4-stage cp.async ring, one barrier/K-step. Grid (2, 782).
// ---------------------------------------------------------------------------
#define MG_STAGE 12288u
#define MG_SMEM  49152

__global__ void __launch_bounds__(256, 2) k_mgemm(int lidx) {
    extern __shared__ char smem[];
    const uint32_t sb = smem_u32(smem);

    const int tid  = threadIdx.x;
    const int wid  = tid >> 5;
    const int lane = tid & 31;
    const int wm   = wid >> 1;          // 0..3
    const int wn   = wid & 1;           // 0..1
    const int    ncol0 = blockIdx.x * 128;
    const size_t row0  = (size_t)blockIdx.y * 128;

    const __half* __restrict__ Wf = g_wf + (size_t)lidx * 65536;

    const int gr = tid >> 1;            // 0..127 (row / ncol)
    const int gk = (tid & 1) * 8;       // fp16 k offset within 16
    const size_t gA = (row0 + gr) * 256 + gk;
    const size_t gB = ((size_t)(ncol0 + gr)) * 256 + gk;
    const uint32_t sOff = (uint32_t)(gr * 48 + gk * 2);

    const int lr = lane & 7;
    const uint32_t offA = (uint32_t)((wm * 32 + lr + ((lane >> 3) & 1) * 8) * 48
                                     + ((lane >> 4) & 1) * 16);
    const uint32_t offB = (uint32_t)((wn * 64 + lr + ((lane >> 4) & 1) * 8) * 48
                                     + ((lane >> 3) & 1) * 16);

    float acc[2][8][4];
    #pragma unroll
    for (int i = 0; i < 2; i++)
        #pragma unroll
        for (int j = 0; j < 8; j++)
            #pragma unroll
            for (int q = 0; q < 4; q++) acc[i][j][q] = 0.f;

    #pragma unroll
    for (int p = 0; p < 3; p++) {
        const uint32_t bo = (uint32_t)p * MG_STAGE;
        const size_t kk = (size_t)p * 16;
        CP16(sb + bo + sOff,         g_act + gA + kk);
        CP16(sb + bo + 6144u + sOff, Wf + gB + kk);
        CP_COMMIT();
    }

    for (int c = 0; c < 16; c++) {
        CP_WAIT2();
        __syncthreads();

        if (c + 3 < 16) {
            const uint32_t bo = (uint32_t)((c + 3) & 3) * MG_STAGE;
            const size_t kk = (size_t)(c + 3) * 16;
            CP16(sb + bo + sOff,         g_act + gA + kk);
            CP16(sb + bo + 6144u + sOff, Wf + gB + kk);
        }
        CP_COMMIT();

        const uint32_t base  = sb + (uint32_t)(c & 3) * MG_STAGE;
        const uint32_t aBase = base + offA;
        const uint32_t bBase = base + 6144u + offB;

        uint32_t ah[2][4], bh[8][2];
        #pragma unroll
        for (int mi = 0; mi < 2; mi++)
            LDSM4(ah[mi][0], ah[mi][1], ah[mi][2], ah[mi][3], aBase + mi * 768u);
        #pragma unroll
        for (int j = 0; j < 4; j++) {
            uint32_t t0, t1, t2, t3;
            LDSM4(t0, t1, t2, t3, bBase + j * 768u);
            bh[2 * j][0] = t0; bh[2 * j][1] = t1;
            bh[2 * j + 1][0] = t2; bh[2 * j + 1][1] = t3;
        }

        #pragma unroll
        for (int mi = 0; mi < 2; mi++)
            #pragma unroll
            for (int nj = 0; nj < 8; nj++)
                MMA16816H(acc[mi][nj], ah[mi], bh[nj]);
    }

    // epilogue: write fp16
    #pragma unroll
    for (int mi = 0; mi < 2; mi++) {
        const size_t r0 = row0 + wm * 32 + mi * 16 + (lane >> 2);
        const int cc0 = ncol0 + wn * 64 + (lane & 3) * 2;
        #pragma unroll
        for (int nj = 0; nj < 8; nj++) {
            const int cc = cc0 + nj * 8;
            if (r0 < NN)
                *(__half2*)&g_gh[r0 * 256 + cc] =
                    __floats2half2_rn(acc[mi][nj][0], acc[mi][nj][1]);
            if (r0 + 8 < NN)
                *(__half2*)&g_gh[(r0 + 8) * 256 + cc] =
                    __floats2half2_rn(acc[mi][nj][2], acc[mi][nj][3]);
        }
    }
}

// ---------------------------------------------------------------------------
// Shared SpMM gather over fp16 rows: lane covers feats [8l..8l+7] via one
// uint4 (16 B) per edge row. Self-loop + bias + relu applied.
// ---------------------------------------------------------------------------
__device__ __forceinline__ void acc8(float* acc, uint4 v, float w) {
    float2 f0 = __half22float2(*(__half2*)&v.x);
    float2 f1 = __half22float2(*(__half2*)&v.y);
    float2 f2 = __half22float2(*(__half2*)&v.z);
    float2 f3 = __half22float2(*(__half2*)&v.w);
    acc[0] += w * f0.x; acc[1] += w * f0.y;
    acc[2] += w * f1.x; acc[3] += w * f1.y;
    acc[4] += w * f2.x; acc[5] += w * f2.y;
    acc[6] += w * f3.x; acc[7] += w * f3.y;
}

__device__ __forceinline__ void spmm_gather(int node, int lane,
                                            const float* __restrict__ bias,
                                            float* acc) {
    const __half* __restrict__ H = g_gh;
    int beg = g_rowptr[node];
    int end = beg + g_deg[node];

    #pragma unroll
    for (int i = 0; i < 8; i++) acc[i] = 0.f;

    int e = beg;
    for (; e + 1 < end; e += 2) {
        int2 p0 = g_edges[e];
        int2 p1 = g_edges[e + 1];
        uint4 v0 = *((const uint4*)(H + (size_t)p0.x * 256) + lane);
        uint4 v1 = *((const uint4*)(H + (size_t)p1.x * 256) + lane);
        acc8(acc, v0, __int_as_float(p0.y));
        acc8(acc, v1, __int_as_float(p1.y));
    }
    for (; e < end; e++) {
        int2 p = g_edges[e];
        uint4 v = *((const uint4*)(H + (size_t)p.x * 256) + lane);
        acc8(acc, v, __int_as_float(p.y));
    }

    // self-loop
    float di = g_dinv[node];
    {
        uint4 v = *((const uint4*)(H + (size_t)node * 256) + lane);
        acc8(acc, v, di * di);
    }

    // bias + relu (lane covers feats 8l..8l+7)
    const float4* bb = (const float4*)bias;
    float4 b0 = bb[2 * lane];
    float4 b1 = bb[2 * lane + 1];
    acc[0] = fmaxf(acc[0] + b0.x, 0.f); acc[1] = fmaxf(acc[1] + b0.y, 0.f);
    acc[2] = fmaxf(acc[2] + b0.z, 0.f); acc[3] = fmaxf(acc[3] + b0.w, 0.f);
    acc[4] = fmaxf(acc[4] + b1.x, 0.f); acc[5] = fmaxf(acc[5] + b1.y, 0.f);
    acc[6] = fmaxf(acc[6] + b1.z, 0.f); acc[7] = fmaxf(acc[7] + b1.w, 0.f);
}

// ---------------------------------------------------------------------------
// SpMM (F=256) for layers 1,2: writes fp16 activations for the next GEMM.
// ---------------------------------------------------------------------------
__global__ void __launch_bounds__(256) k_spmm256(const float* __restrict__ bias) {
    int warp = threadIdx.x >> 5;
    int lane = threadIdx.x & 31;
    int node = blockIdx.x * 8 + warp;
    if (node >= NN) return;

    float acc[8];
    spmm_gather(node, lane, bias, acc);

    uint4 h;
    *(__half2*)&h.x = __floats2half2_rn(acc[0], acc[1]);
    *(__half2*)&h.y = __floats2half2_rn(acc[2], acc[3]);
    *(__half2*)&h.z = __floats2half2_rn(acc[4], acc[5]);
    *(__half2*)&h.w = __floats2half2_rn(acc[6], acc[7]);
    *((uint4*)(g_act + (size_t)node * 256) + lane) = h;
}

// ---------------------------------------------------------------------------
// Layer-3 SpMM fused with the layer-4 linear: h4 = relu(agg3 + b3) @ W4.
// Lane holds feats [8l..8l+7]; W4 k-major in smem (stride 264); butterfly.
// Writes g_h4 as fp16.
// ---------------------------------------------------------------------------
__global__ void __launch_bounds__(256) k_spmm256_w4(const float* __restrict__ bias,
                                                   const float* __restrict__ W4) {
    __shared__ float Ws[16 * 264];   // Ws[c*264 + k] = W4[k*16 + c]
    for (int idx = threadIdx.x; idx < 4096; idx += 256) {
        int k = idx >> 4, c = idx & 15;
        Ws[c * 264 + k] = W4[idx];
    }
    __syncthreads();

    int warp = threadIdx.x >> 5;
    int lane = threadIdx.x & 31;
    int node = blockIdx.x * 8 + warp;
    if (node >= NN) return;

    float acc[8];
    spmm_gather(node, lane, bias, acc);

    float p[16];
    #pragma unroll
    for (int c = 0; c < 16; c++) {
        float4 w0 = *(const float4*)&Ws[c * 264 + 8 * lane];
        float4 w1 = *(const float4*)&Ws[c * 264 + 8 * lane + 4];
        p[c] = acc[0] * w0.x + acc[1] * w0.y + acc[2] * w0.z + acc[3] * w0.w
             + acc[4] * w1.x + acc[5] * w1.y + acc[6] * w1.z + acc[7] * w1.w;
    }
    #pragma unroll
    for (int off = 16; off > 0; off >>= 1)
        #pragma unroll
        for (int c = 0; c < 16; c++)
            p[c] += __shfl_xor_sync(0xffffffffu, p[c], off);

    if (lane < 16)
        g_h4[(size_t)node * 16 + lane] = __float2half_rn(p[lane]);
}

// ---------------------------------------------------------------------------
// SpMM (F=16) + bias + log_softmax -> final output (reads g_h4, fp16)
// ---------------------------------------------------------------------------
__global__ void __launch_bounds__(256) k_spmm16(const float* __restrict__ bias,
                                               float* __restrict__ out) {
    const __half* __restrict__ H = g_h4;

    int warp = threadIdx.x >> 5;
    int lane = threadIdx.x & 31;
    int node = blockIdx.x * 8 + warp;
    if (node >= NN) return;

    int f = lane & 15;
    int beg = g_rowptr[node];
    int end = beg + g_deg[node];

    float acc = 0.f;
    for (int e = beg; e < end; e++) {
        int2 p = g_edges[e];
        acc += __int_as_float(p.y) * __half2float(H[(size_t)p.x * 16 + f]);
    }
    float di = g_dinv[node];
    acc += di * di * __half2float(H[(size_t)node * 16 + f]);
    acc += bias[f];

    float m = acc;
    #pragma unroll
    for (int o = 8; o > 0; o >>= 1)
        m = fmaxf(m, __shfl_xor_sync(0xffffffffu, m, o, 16));
    float ex = expf(acc - m);
    float s = ex;
    #pragma unroll
    for (int o = 8; o > 0; o >>= 1)
        s += __shfl_xor_sync(0xffffffffu, s, o, 16);

    if (lane < 16)
        out[(size_t)node * 16 + f] = (acc - m) - logf(s);
}

// ---------------------------------------------------------------------------
// Launcher — single stream (r15 structure; 1-kernel CSR offsets)
// ---------------------------------------------------------------------------
extern "C" void kernel_launch(void* const* d_in, const int* in_sizes, int n_in,
                              void* d_out, int out_size)
{
    const float* x  = (const float*)d_in[0];
    const int*   ei = (const int*)  d_in[1];
    const float* W1 = (const float*)d_in[2];
    const float* b1 = (const float*)d_in[3];
    const float* W2 = (const float*)d_in[4];
    const float* b2 = (const float*)d_in[5];
    const float* W3 = (const float*)d_in[6];
    const float* b3 = (const float*)d_in[7];
    const float* W4 = (const float*)d_in[8];
    const float* b4 = (const float*)d_in[9];
    float* out = (float*)d_out;

    static int s_attr_done = 0;
    if (!s_attr_done) {
        cudaFuncSetAttribute(k_mgemm, cudaFuncAttributeMaxDynamicSharedMemorySize, MG_SMEM);
        s_attr_done = 1;
    }

    const int NB_SCAN = (NN + 1023) / 1024;   // 98
    const int sgrid = (NN + 7) / 8;           // 12500

    // prep: zero(g_deg, g_alloc) + W->fp16 + x->fp16 (independent, one kernel)
    k_prep   <<<26159, 256>>>(x, W1, W2, W3);

    // graph preprocessing
    k_hist   <<<(EE + 255) / 256, 256>>>(ei);
    k_csr    <<<NB_SCAN, 1024>>>();
    k_scatter<<<(EE + 255) / 256, 256>>>(ei);

    dim3 ggrid(2, MPAD / 128);                // N-split fastest (L2 reuse of A)

    // layer 1
    k_mgemm  <<<ggrid, 256, MG_SMEM>>>(0);
    k_spmm256<<<sgrid, 256>>>(b1);
    // layer 2
    k_mgemm  <<<ggrid, 256, MG_SMEM>>>(1);
    k_spmm256<<<sgrid, 256>>>(b2);
    // layer 3 (+ fused layer-4 linear)
    k_mgemm  <<<ggrid, 256, MG_SMEM>>>(2);
    k_spmm256_w4<<<sgrid, 256>>>(b3, W4);
    // layer 4 aggregate + log_softmax
    k_spmm16 <<<sgrid, 256>>>(b4, out);
}

// round 17
// speedup vs baseline: 1.2345x; 1.0294x over previous
#include <cuda_runtime.h>
#include <cuda_bf16.h>
#include <cuda_fp16.h>
#include <math.h>
#include <stdint.h>

// Problem constants (fixed by reference)
#define NN   100000
#define EE   1600000
#define MPAD 100096   // 782 * 128

// ---------------------------------------------------------------------------
// Scratch (__device__ globals; no runtime allocation)
// ---------------------------------------------------------------------------
__device__ __half g_gh[(size_t)MPAD * 256];    // GEMM output pre-scaled by dinv (fp16)
__device__ __half g_act[(size_t)MPAD * 256];   // activations (fp16) / GEMM A input
__device__ __half g_wf[3 * 256 * 256];         // W^T per layer (n-major, k contig, fp16)
__device__ __half g_h4[(size_t)NN * 16];       // fused layer-4 pre-agg, pre-scaled (fp16)
__device__ int    g_deg[NN];
__device__ float  g_dinv[NN];
__device__ int    g_rowptr[NN];                // segment start per node (disjoint)
__device__ int    g_cursor[NN];
__device__ int    g_alloc;                     // global segment allocator
__device__ int    g_edges[EE];                 // src only (dinv folded into rows)

// ---------------------------------------------------------------------------
// PTX helpers (sm_80-era; valid on plain compute_100 target)
// ---------------------------------------------------------------------------
__device__ __forceinline__ uint32_t smem_u32(const void* p) {
    uint32_t a;
    asm("{ .reg .u64 t; cvta.to.shared.u64 t, %1; cvt.u32.u64 %0, t; }"
        : "=r"(a) : "l"(p));
    return a;
}

#define CP16(smem_addr, gptr) \
    asm volatile("cp.async.cg.shared.global [%0], [%1], 16;" \
        :: "r"(smem_addr), "l"(gptr) : "memory")
#define CP_COMMIT() asm volatile("cp.async.commit_group;" ::: "memory")
#define CP_WAIT2()  asm volatile("cp.async.wait_group 2;" ::: "memory")

#define LDSM4(r0, r1, r2, r3, addr) \
    asm volatile("ldmatrix.sync.aligned.m8n8.x4.shared.b16 {%0,%1,%2,%3}, [%4];" \
        : "=r"(r0), "=r"(r1), "=r"(r2), "=r"(r3) : "r"(addr))

#define MMA16816H(d, a, b) \
    asm volatile("mma.sync.aligned.m16n8k16.row.col.f32.f16.f16.f32 " \
        "{%0,%1,%2,%3},{%4,%5,%6,%7},{%8,%9},{%0,%1,%2,%3};" \
        : "+f"((d)[0]), "+f"((d)[1]), "+f"((d)[2]), "+f"((d)[3]) \
        : "r"((a)[0]), "r"((a)[1]), "r"((a)[2]), "r"((a)[3]), \
          "r"((b)[0]), "r"((b)[1]))

// ---------------------------------------------------------------------------
// k_prep: fused zero(g_deg, g_alloc) + W->fp16 transpose + x->fp16 convert
// blocks [0,391): zero; [391,1159): wconv; [1159,26159): xconv
// ---------------------------------------------------------------------------
__global__ void __launch_bounds__(256) k_prep(const float* __restrict__ x,
                                             const float* __restrict__ W1,
                                             const float* __restrict__ W2,
                                             const float* __restrict__ W3) {
    int bid = blockIdx.x;
    if (bid < 391) {
        int i = bid * 256 + threadIdx.x;
        if (i < NN) g_deg[i] = 0;
        if (bid == 0 && threadIdx.x == 0) g_alloc = 0;
    } else if (bid < 1159) {
        int idx = (bid - 391) * 256 + threadIdx.x;   // 0..196607
        int l = idx >> 16;
        int r = idx & 65535;
        int k = r >> 8, n = r & 255;
        const float* W = (l == 0) ? W1 : ((l == 1) ? W2 : W3);
        g_wf[l * 65536 + n * 256 + k] = __float2half_rn(W[k * 256 + n]);
    } else {
        size_t i = (size_t)(bid - 1159) * 256 + threadIdx.x;   // float4 index
        if (i < (size_t)NN * 64) {
            float4 v = ((const float4*)x)[i];
            uint2 h;
            *(__half2*)&h.x = __floats2half2_rn(v.x, v.y);
            *(__half2*)&h.y = __floats2half2_rn(v.z, v.w);
            *(uint2*)(g_act + i * 4) = h;
        }
    }
}

// ---------------------------------------------------------------------------
// Graph preprocessing
// ---------------------------------------------------------------------------
__global__ void k_hist(const int* __restrict__ ei) {
    int e = blockIdx.x * blockDim.x + threadIdx.x;
    if (e < EE) atomicAdd(&g_deg[ei[EE + e]], 1);
}

// Single-kernel CSR offsets: per-block scan + one global atomicAdd per block.
__global__ void k_csr() {
    __shared__ int sh[1024];
    __shared__ int base;
    int i = blockIdx.x * 1024 + threadIdx.x;
    int v = (i < NN) ? g_deg[i] : 0;
    if (i < NN) {
        g_dinv[i] = rsqrtf((float)v + 1.0f);
        g_cursor[i] = 0;
    }
    sh[threadIdx.x] = v;
    __syncthreads();
    #pragma unroll
    for (int off = 1; off < 1024; off <<= 1) {
        int t = (threadIdx.x >= off) ? sh[threadIdx.x - off] : 0;
        __syncthreads();
        sh[threadIdx.x] += t;
        __syncthreads();
    }
    if (threadIdx.x == 1023) base = atomicAdd(&g_alloc, sh[1023]);
    __syncthreads();
    if (i < NN) g_rowptr[i] = base + sh[threadIdx.x] - v;
}

// Scatter: src only (4 B/edge); no dinv reads, no norm math.
__global__ void k_scatter(const int* __restrict__ ei) {
    int e = blockIdx.x * blockDim.x + threadIdx.x;
    if (e >= EE) return;
    int s = ei[e];
    int d = ei[EE + e];
    int pos = g_rowptr[d] + atomicAdd(&g_cursor[d], 1);
    g_edges[pos] = s;
}

// ---------------------------------------------------------------------------
// fp16 tensor GEMM via mma.sync (fp32 accumulate):
//   g_gh[M x 256] (fp16) = dinv[row] * (g_act[M x 256] @ W[256 x 256])
// CTA tile 128x128, 8 warps (4m x 2n), warp tile 32x64, K-step 16.
// 4-stage cp.async ring, one barrier/K-step. Grid (2, 782).
// ---------------------------------------------------------------------------
#define MG_STAGE 12288u
#define MG_SMEM  49152

__global__ void __launch_bounds__(256, 2) k_mgemm(int lidx) {
    extern __shared__ char smem[];
    const uint32_t sb = smem_u32(smem);

    const int tid  = threadIdx.x;
    const int wid  = tid >> 5;
    const int lane = tid & 31;
    const int wm   = wid >> 1;          // 0..3
    const int wn   = wid & 1;           // 0..1
    const int    ncol0 = blockIdx.x * 128;
    const size_t row0  = (size_t)blockIdx.y * 128;

    const __half* __restrict__ Wf = g_wf + (size_t)lidx * 65536;

    const int gr = tid >> 1;            // 0..127 (row / ncol)
    const int gk = (tid & 1) * 8;       // fp16 k offset within 16
    const size_t gA = (row0 + gr) * 256 + gk;
    const size_t gB = ((size_t)(ncol0 + gr)) * 256 + gk;
    const uint32_t sOff = (uint32_t)(gr * 48 + gk * 2);

    const int lr = lane & 7;
    const uint32_t offA = (uint32_t)((wm * 32 + lr + ((lane >> 3) & 1) * 8) * 48
                                     + ((lane >> 4) & 1) * 16);
    const uint32_t offB = (uint32_t)((wn * 64 + lr + ((lane >> 4) & 1) * 8) * 48
                                     + ((lane >> 3) & 1) * 16);

    float acc[2][8][4];
    #pragma unroll
    for (int i = 0; i < 2; i++)
        #pragma unroll
        for (int j = 0; j < 8; j++)
            #pragma unroll
            for (int q = 0; q < 4; q++) acc[i][j][q] = 0.f;

    #pragma unroll
    for (int p = 0; p < 3; p++) {
        const uint32_t bo = (uint32_t)p * MG_STAGE;
        const size_t kk = (size_t)p * 16;
        CP16(sb + bo + sOff,         g_act + gA + kk);
        CP16(sb + bo + 6144u + sOff, Wf + gB + kk);
        CP_COMMIT();
    }

    for (int c = 0; c < 16; c++) {
        CP_WAIT2();
        __syncthreads();

        if (c + 3 < 16) {
            const uint32_t bo = (uint32_t)((c + 3) & 3) * MG_STAGE;
            const size_t kk = (size_t)(c + 3) * 16;
            CP16(sb + bo + sOff,         g_act + gA + kk);
            CP16(sb + bo + 6144u + sOff, Wf + gB + kk);
        }
        CP_COMMIT();

        const uint32_t base  = sb + (uint32_t)(c & 3) * MG_STAGE;
        const uint32_t aBase = base + offA;
        const uint32_t bBase = base + 6144u + offB;

        uint32_t ah[2][4], bh[8][2];
        #pragma unroll
        for (int mi = 0; mi < 2; mi++)
            LDSM4(ah[mi][0], ah[mi][1], ah[mi][2], ah[mi][3], aBase + mi * 768u);
        #pragma unroll
        for (int j = 0; j < 4; j++) {
            uint32_t t0, t1, t2, t3;
            LDSM4(t0, t1, t2, t3, bBase + j * 768u);
            bh[2 * j][0] = t0; bh[2 * j][1] = t1;
            bh[2 * j + 1][0] = t2; bh[2 * j + 1][1] = t3;
        }

        #pragma unroll
        for (int mi = 0; mi < 2; mi++)
            #pragma unroll
            for (int nj = 0; nj < 8; nj++)
                MMA16816H(acc[mi][nj], ah[mi], bh[nj]);
    }

    // epilogue: scale by dinv[row], write fp16
    #pragma unroll
    for (int mi = 0; mi < 2; mi++) {
        const size_t r0 = row0 + wm * 32 + mi * 16 + (lane >> 2);
        const int cc0 = ncol0 + wn * 64 + (lane & 3) * 2;
        const float dv0 = (r0 < NN)     ? g_dinv[r0]     : 0.f;
        const float dv1 = (r0 + 8 < NN) ? g_dinv[r0 + 8] : 0.f;
        #pragma unroll
        for (int nj = 0; nj < 8; nj++) {
            const int cc = cc0 + nj * 8;
            if (r0 < NN)
                *(__half2*)&g_gh[r0 * 256 + cc] =
                    __floats2half2_rn(acc[mi][nj][0] * dv0, acc[mi][nj][1] * dv0);
            if (r0 + 8 < NN)
                *(__half2*)&g_gh[(r0 + 8) * 256 + cc] =
                    __floats2half2_rn(acc[mi][nj][2] * dv1, acc[mi][nj][3] * dv1);
        }
    }
}

// ---------------------------------------------------------------------------
// Shared SpMM gather over pre-scaled fp16 rows H': lane covers feats
// [8l..8l+7] via one uint4 per edge row. Unweighted sum; final
// agg = dinv[node] * (sum + H'[node]) + bias, relu.
// ---------------------------------------------------------------------------
__device__ __forceinline__ void acc8(float* acc, uint4 v) {
    float2 f0 = __half22float2(*(__half2*)&v.x);
    float2 f1 = __half22float2(*(__half2*)&v.y);
    float2 f2 = __half22float2(*(__half2*)&v.z);
    float2 f3 = __half22float2(*(__half2*)&v.w);
    acc[0] += f0.x; acc[1] += f0.y;
    acc[2] += f1.x; acc[3] += f1.y;
    acc[4] += f2.x; acc[5] += f2.y;
    acc[6] += f3.x; acc[7] += f3.y;
}

__device__ __forceinline__ void spmm_gather(int node, int lane,
                                            const float* __restrict__ bias,
                                            float* acc) {
    const __half* __restrict__ H = g_gh;
    int beg = g_rowptr[node];
    int end = beg + g_deg[node];

    #pragma unroll
    for (int i = 0; i < 8; i++) acc[i] = 0.f;

    int e = beg;
    for (; e + 1 < end; e += 2) {
        int s0 = g_edges[e];
        int s1 = g_edges[e + 1];
        uint4 v0 = *((const uint4*)(H + (size_t)s0 * 256) + lane);
        uint4 v1 = *((const uint4*)(H + (size_t)s1 * 256) + lane);
        acc8(acc, v0);
        acc8(acc, v1);
    }
    for (; e < end; e++) {
        uint4 v = *((const uint4*)(H + (size_t)g_edges[e] * 256) + lane);
        acc8(acc, v);
    }

    // self-loop (H' already carries dinv[node])
    {
        uint4 v = *((const uint4*)(H + (size_t)node * 256) + lane);
        acc8(acc, v);
    }

    // final scale + bias + relu (lane covers feats 8l..8l+7)
    float dn = g_dinv[node];
    const float4* bb = (const float4*)bias;
    float4 b0 = bb[2 * lane];
    float4 b1 = bb[2 * lane + 1];
    acc[0] = fmaxf(acc[0] * dn + b0.x, 0.f); acc[1] = fmaxf(acc[1] * dn + b0.y, 0.f);
    acc[2] = fmaxf(acc[2] * dn + b0.z, 0.f); acc[3] = fmaxf(acc[3] * dn + b0.w, 0.f);
    acc[4] = fmaxf(acc[4] * dn + b1.x, 0.f); acc[5] = fmaxf(acc[5] * dn + b1.y, 0.f);
    acc[6] = fmaxf(acc[6] * dn + b1.z, 0.f); acc[7] = fmaxf(acc[7] * dn + b1.w, 0.f);
}

// ---------------------------------------------------------------------------
// SpMM (F=256) for layers 1,2: writes fp16 activations for the next GEMM.
// ---------------------------------------------------------------------------
__global__ void __launch_bounds__(256) k_spmm256(const float* __restrict__ bias) {
    int warp = threadIdx.x >> 5;
    int lane = threadIdx.x & 31;
    int node = blockIdx.x * 8 + warp;
    if (node >= NN) return;

    float acc[8];
    spmm_gather(node, lane, bias, acc);

    uint4 h;
    *(__half2*)&h.x = __floats2half2_rn(acc[0], acc[1]);
    *(__half2*)&h.y = __floats2half2_rn(acc[2], acc[3]);
    *(__half2*)&h.z = __floats2half2_rn(acc[4], acc[5]);
    *(__half2*)&h.w = __floats2half2_rn(acc[6], acc[7]);
    *((uint4*)(g_act + (size_t)node * 256) + lane) = h;
}

// ---------------------------------------------------------------------------
// Layer-3 SpMM fused with the layer-4 linear: h4 = relu(agg3 + b3) @ W4,
// stored pre-scaled: g_h4[node] = dinv[node] * h4[node] (fp16).
// ---------------------------------------------------------------------------
__global__ void __launch_bounds__(256) k_spmm256_w4(const float* __restrict__ bias,
                                                   const float* __restrict__ W4) {
    __shared__ float Ws[16 * 264];   // Ws[c*264 + k] = W4[k*16 + c]
    for (int idx = threadIdx.x; idx < 4096; idx += 256) {
        int k = idx >> 4, c = idx & 15;
        Ws[c * 264 + k] = W4[idx];
    }
    __syncthreads();

    int warp = threadIdx.x >> 5;
    int lane = threadIdx.x & 31;
    int node = blockIdx.x * 8 + warp;
    if (node >= NN) return;

    float acc[8];
    spmm_gather(node, lane, bias, acc);

    float p[16];
    #pragma unroll
    for (int c = 0; c < 16; c++) {
        float4 w0 = *(const float4*)&Ws[c * 264 + 8 * lane];
        float4 w1 = *(const float4*)&Ws[c * 264 + 8 * lane + 4];
        p[c] = acc[0] * w0.x + acc[1] * w0.y + acc[2] * w0.z + acc[3] * w0.w
             + acc[4] * w1.x + acc[5] * w1.y + acc[6] * w1.z + acc[7] * w1.w;
    }
    #pragma unroll
    for (int off = 16; off > 0; off >>= 1)
        #pragma unroll
        for (int c = 0; c < 16; c++)
            p[c] += __shfl_xor_sync(0xffffffffu, p[c], off);

    if (lane < 16)
        g_h4[(size_t)node * 16 + lane] = __float2half_rn(p[lane] * g_dinv[node]);
}

// ---------------------------------------------------------------------------
// SpMM (F=16) + bias + log_softmax -> final output (g_h4 pre-scaled fp16)
// ---------------------------------------------------------------------------
__global__ void __launch_bounds__(256) k_spmm16(const float* __restrict__ bias,
                                               float* __restrict__ out) {
    const __half* __restrict__ H = g_h4;

    int warp = threadIdx.x >> 5;
    int lane = threadIdx.x & 31;
    int node = blockIdx.x * 8 + warp;
    if (node >= NN) return;

    int f = lane & 15;
    int beg = g_rowptr[node];
    int end = beg + g_deg[node];

    float acc = 0.f;
    for (int e = beg; e < end; e++) {
        int s = g_edges[e];
        acc += __half2float(H[(size_t)s * 16 + f]);
    }
    acc += __half2float(H[(size_t)node * 16 + f]);
    acc = acc * g_dinv[node] + bias[f];

    float m = acc;
    #pragma unroll
    for (int o = 8; o > 0; o >>= 1)
        m = fmaxf(m, __shfl_xor_sync(0xffffffffu, m, o, 16));
    float ex = expf(acc - m);
    float s = ex;
    #pragma unroll
    for (int o = 8; o > 0; o >>= 1)
        s += __shfl_xor_sync(0xffffffffu, s, o, 16);

    if (lane < 16)
        out[(size_t)node * 16 + f] = (acc - m) - logf(s);
}

// ---------------------------------------------------------------------------
// Launcher — single stream (dinv folded into rows; src-only edges)
// ---------------------------------------------------------------------------
extern "C" void kernel_launch(void* const* d_in, const int* in_sizes, int n_in,
                              void* d_out, int out_size)
{
    const float* x  = (const float*)d_in[0];
    const int*   ei = (const int*)  d_in[1];
    const float* W1 = (const float*)d_in[2];
    const float* b1 = (const float*)d_in[3];
    const float* W2 = (const float*)d_in[4];
    const float* b2 = (const float*)d_in[5];
    const float* W3 = (const float*)d_in[6];
    const float* b3 = (const float*)d_in[7];
    const float* W4 = (const float*)d_in[8];
    const float* b4 = (const float*)d_in[9];
    float* out = (float*)d_out;

    static int s_attr_done = 0;
    if (!s_attr_done) {
        cudaFuncSetAttribute(k_mgemm, cudaFuncAttributeMaxDynamicSharedMemorySize, MG_SMEM);
        s_attr_done = 1;
    }

    const int NB_SCAN = (NN + 1023) / 1024;   // 98
    const int sgrid = (NN + 7) / 8;           // 12500

    // prep: zero(g_deg, g_alloc) + W->fp16 + x->fp16 (independent, one kernel)
    k_prep   <<<26159, 256>>>(x, W1, W2, W3);

    // graph preprocessing
    k_hist   <<<(EE + 255) / 256, 256>>>(ei);
    k_csr    <<<NB_SCAN, 1024>>>();
    k_scatter<<<(EE + 255) / 256, 256>>>(ei);

    dim3 ggrid(2, MPAD / 128);                // N-split fastest (L2 reuse of A)

    // layer 1
    k_mgemm  <<<ggrid, 256, MG_SMEM>>>(0);
    k_spmm256<<<sgrid, 256>>>(b1);
    // layer 2
    k_mgemm  <<<ggrid, 256, MG_SMEM>>>(1);
    k_spmm256<<<sgrid, 256>>>(b2);
    // layer 3 (+ fused layer-4 linear)
    k_mgemm  <<<ggrid, 256, MG_SMEM>>>(2);
    k_spmm256_w4<<<sgrid, 256>>>(b3, W4);
    // layer 4 aggregate + log_softmax
    k_spmm16 <<<sgrid, 256>>>(b4, out);
}